// round 1
// baseline (speedup 1.0000x reference)
#include <cuda_runtime.h>
#include <cuda_bf16.h>
#include <math.h>

// ---------------------------------------------------------------------------
// FusedGatedDeltaNet: B=1, S=1024, D_IN=2048, H_QK=8, H_V=16, DK=DV=128,
// KCONV=4, FUSED=4096, D_OUT=1024, D_OUT_VG=2048
// ---------------------------------------------------------------------------

#define SEQ   1024
#define DIN   2048
#define FUSEDC 4096
#define HQK   8
#define HV    16
#define DK    128
#define DV    128
#define DOVG  2048

// scratch (static device arrays; no allocation)
__device__ float g_qkv_pre[SEQ * FUSEDC];   // x @ w_qkv^T
__device__ float g_qkv[SEQ * FUSEDC];       // after conv + silu (+ l2norm in place)
__device__ float g_gate[SEQ * DOVG];        // silu(x @ w_gate^T)
__device__ float g_ctx[SEQ * DOVG];         // scan output
__device__ float g_gctx[SEQ * DOVG];        // rms(ctx)*rms_w*gate
__device__ float g_beta[HV * SEQ];
__device__ float g_alpha[HV * SEQ];

// ---------------------------------------------------------------------------
// SGEMM: C[m,n] = sum_k A[m*K+k] * B[n*K+k]   (A row-major MxK, B row-major NxK)
// BM=BN=128, BK=16, 256 threads, 8x8 per thread. epi: 0=none, 1=silu
// ---------------------------------------------------------------------------
__global__ void __launch_bounds__(256) sgemm_nt(
    const float* __restrict__ A, const float* __restrict__ B,
    float* __restrict__ C, int M, int N, int K, int epi)
{
    __shared__ float As[16][128];
    __shared__ float Bs[16][128];

    const int tid = threadIdx.x;
    const int bm = blockIdx.y * 128;
    const int bn = blockIdx.x * 128;
    const int tx = tid & 15;    // col group
    const int ty = tid >> 4;    // row group

    float acc[8][8];
#pragma unroll
    for (int i = 0; i < 8; ++i)
#pragma unroll
        for (int j = 0; j < 8; ++j) acc[i][j] = 0.f;

    for (int k0 = 0; k0 < K; k0 += 16) {
#pragma unroll
        for (int it = 0; it < 2; ++it) {
            int lin = tid + it * 256;        // 0..511
            int row = lin >> 2;              // 0..127
            int c4  = (lin & 3) << 2;        // 0,4,8,12
            float4 va = *(const float4*)(A + (size_t)(bm + row) * K + k0 + c4);
            As[c4 + 0][row] = va.x; As[c4 + 1][row] = va.y;
            As[c4 + 2][row] = va.z; As[c4 + 3][row] = va.w;
            float4 vb = *(const float4*)(B + (size_t)(bn + row) * K + k0 + c4);
            Bs[c4 + 0][row] = vb.x; Bs[c4 + 1][row] = vb.y;
            Bs[c4 + 2][row] = vb.z; Bs[c4 + 3][row] = vb.w;
        }
        __syncthreads();

#pragma unroll
        for (int kk = 0; kk < 16; ++kk) {
            float ra[8], rb[8];
#pragma unroll
            for (int i = 0; i < 8; ++i) ra[i] = As[kk][ty * 8 + i];
#pragma unroll
            for (int j = 0; j < 8; ++j) rb[j] = Bs[kk][tx * 8 + j];
#pragma unroll
            for (int i = 0; i < 8; ++i)
#pragma unroll
                for (int j = 0; j < 8; ++j)
                    acc[i][j] = fmaf(ra[i], rb[j], acc[i][j]);
        }
        __syncthreads();
    }

#pragma unroll
    for (int i = 0; i < 8; ++i) {
        int r = bm + ty * 8 + i;
#pragma unroll
        for (int j = 0; j < 8; ++j) {
            int c = bn + tx * 8 + j;
            float v = acc[i][j];
            if (epi == 1) v = v / (1.f + expf(-v));   // silu
            C[(size_t)r * N + c] = v;
        }
    }
}

// ---------------------------------------------------------------------------
// beta / alpha projections: per token t, 32 dot products of length 2048
// ---------------------------------------------------------------------------
__global__ void __launch_bounds__(256) beta_alpha_kernel(
    const float* __restrict__ x, const float* __restrict__ w_beta,
    const float* __restrict__ w_alpha, const float* __restrict__ log_A,
    const float* __restrict__ dt_bias,
    float* __restrict__ beta, float* __restrict__ alpha)
{
    const int t = blockIdx.x;
    const int warp = threadIdx.x >> 5;
    const int lane = threadIdx.x & 31;
    const float* xr = x + (size_t)t * DIN;

#pragma unroll
    for (int d = 0; d < 4; ++d) {
        int idx = warp + (d << 3);   // 0..31
        const float* w = (idx < 16) ? (w_beta + (size_t)idx * DIN)
                                    : (w_alpha + (size_t)(idx - 16) * DIN);
        float s = 0.f;
        for (int k = lane; k < DIN; k += 32) s = fmaf(xr[k], w[k], s);
#pragma unroll
        for (int m = 16; m; m >>= 1) s += __shfl_xor_sync(0xffffffffu, s, m);
        if (lane == 0) {
            if (idx < 16) {
                beta[idx * SEQ + t] = 1.f / (1.f + expf(-s));
            } else {
                int h = idx - 16;
                float z = s + dt_bias[h];
                float sp = (z > 20.f) ? z : log1pf(expf(z));
                alpha[h * SEQ + t] = expf(-expf(log_A[h]) * sp);
            }
        }
    }
}

// ---------------------------------------------------------------------------
// causal depthwise conv1d (K=4, left pad 3) + SiLU
// ---------------------------------------------------------------------------
__global__ void __launch_bounds__(256) conv_silu_kernel(
    const float* __restrict__ in, const float* __restrict__ w,
    float* __restrict__ out)
{
    int idx = blockIdx.x * 256 + threadIdx.x;   // SEQ*FUSEDC
    int c = idx & (FUSEDC - 1);
    int t = idx >> 12;
    float4 wc = *(const float4*)(w + c * 4);
    float s = wc.w * in[(size_t)t * FUSEDC + c];
    if (t >= 1) s = fmaf(wc.z, in[(size_t)(t - 1) * FUSEDC + c], s);
    if (t >= 2) s = fmaf(wc.y, in[(size_t)(t - 2) * FUSEDC + c], s);
    if (t >= 3) s = fmaf(wc.x, in[(size_t)(t - 3) * FUSEDC + c], s);
    out[idx] = s / (1.f + expf(-s));
}

// ---------------------------------------------------------------------------
// L2-normalize q and k head groups in place; fold DK^-0.5 into q
// grid: (SEQ, 16)  [g<8: q head g, g>=8: k head g-8], 128 threads
// ---------------------------------------------------------------------------
__global__ void __launch_bounds__(128) l2norm_kernel(float* __restrict__ qkv)
{
    const int t = blockIdx.x;
    const int g = blockIdx.y;
    const int tid = threadIdx.x;
    size_t base = (size_t)t * FUSEDC + g * 128;
    float v = qkv[base + tid];
    float ss = v * v;
#pragma unroll
    for (int m = 16; m; m >>= 1) ss += __shfl_xor_sync(0xffffffffu, ss, m);
    __shared__ float sw[4];
    if ((tid & 31) == 0) sw[tid >> 5] = ss;
    __syncthreads();
    float tot = sw[0] + sw[1] + sw[2] + sw[3];
    float sc = rsqrtf(tot + 1e-6f);
    if (g < 8) sc *= 0.08838834764831845f;   // 128^-0.5
    qkv[base + tid] = v * sc;
}

// ---------------------------------------------------------------------------
// Gated delta-rule scan.
// grid: 128 CTAs = 16 heads x 8 column blocks (16 cols each). 256 threads.
// Thread layout: warp w, lane l -> column j = 2w + (l>>4), sub = l&15.
// Each thread keeps 8 state rows (sub + 16*i) of its column in registers.
// ---------------------------------------------------------------------------
#define TSCHUNK 32
__global__ void __launch_bounds__(256) scan_kernel(
    const float* __restrict__ qkv, const float* __restrict__ beta,
    const float* __restrict__ alpha, float* __restrict__ ctx)
{
    const int h  = blockIdx.x >> 3;
    const int cb = blockIdx.x & 7;
    const int hq = h >> 1;                 // rep = 2
    const int tid  = threadIdx.x;
    const int lane = tid & 31;
    const int warp = tid >> 5;
    const int j    = (warp << 1) | (lane >> 4);   // 0..15
    const int sub  = lane & 15;

    __shared__ float sk[TSCHUNK][128];
    __shared__ float sq[TSCHUNK][128];
    __shared__ float sv[TSCHUNK][16];
    __shared__ float sb[TSCHUNK], sa[TSCHUNK];

    float S[8];
#pragma unroll
    for (int i = 0; i < 8; ++i) S[i] = 0.f;

    const float* qbase = qkv + hq * 128;
    const float* kbase = qkv + 1024 + hq * 128;
    const float* vbase = qkv + 2048 + h * 128 + cb * 16;
    float* obase = ctx + h * 128 + cb * 16 + j;

    for (int t0 = 0; t0 < SEQ; t0 += TSCHUNK) {
        __syncthreads();   // previous chunk fully consumed
#pragma unroll
        for (int u = 0; u < (TSCHUNK * 128) / 256; ++u) {
            int lin = tid + u * 256;
            int tt = lin >> 7, d = lin & 127;
            size_t off = (size_t)(t0 + tt) * FUSEDC + d;
            sq[tt][d] = qbase[off];
            sk[tt][d] = kbase[off];
        }
#pragma unroll
        for (int u = 0; u < 2; ++u) {
            int lin = tid + u * 256;      // 0..511
            int tt = lin >> 4, jj = lin & 15;
            sv[tt][jj] = vbase[(size_t)(t0 + tt) * FUSEDC + jj];
        }
        if (tid < TSCHUNK) {
            sb[tid] = beta[h * SEQ + t0 + tid];
            sa[tid] = alpha[h * SEQ + t0 + tid];
        }
        __syncthreads();

        for (int tt = 0; tt < TSCHUNK; ++tt) {
            float a = sa[tt], b = sb[tt];
            float kr[8], qr[8];
#pragma unroll
            for (int i = 0; i < 8; ++i) {
                kr[i] = sk[tt][sub + (i << 4)];
                qr[i] = sq[tt][sub + (i << 4)];
            }
            // kv = k . S[:,j]  (pre-decay; multiply by alpha after)
            float kv0 = 0.f, kv1 = 0.f;
#pragma unroll
            for (int i = 0; i < 8; i += 2) {
                kv0 = fmaf(kr[i],     S[i],     kv0);
                kv1 = fmaf(kr[i + 1], S[i + 1], kv1);
            }
            float kv = kv0 + kv1;
            kv += __shfl_xor_sync(0xffffffffu, kv, 1);
            kv += __shfl_xor_sync(0xffffffffu, kv, 2);
            kv += __shfl_xor_sync(0xffffffffu, kv, 4);
            kv += __shfl_xor_sync(0xffffffffu, kv, 8);
            float uval = (sv[tt][j] - a * kv) * b;
            // S = a*S + k u   ;  o = q . S
            float o0 = 0.f, o1 = 0.f;
#pragma unroll
            for (int i = 0; i < 8; ++i)
                S[i] = fmaf(a, S[i], kr[i] * uval);
#pragma unroll
            for (int i = 0; i < 8; i += 2) {
                o0 = fmaf(qr[i],     S[i],     o0);
                o1 = fmaf(qr[i + 1], S[i + 1], o1);
            }
            float o = o0 + o1;
            o += __shfl_xor_sync(0xffffffffu, o, 1);
            o += __shfl_xor_sync(0xffffffffu, o, 2);
            o += __shfl_xor_sync(0xffffffffu, o, 4);
            o += __shfl_xor_sync(0xffffffffu, o, 8);
            if (sub == 0) obase[(size_t)(t0 + tt) * DOVG] = o;
        }
    }
}

// ---------------------------------------------------------------------------
// rms_norm(ctx) * rms_w * gate  -> gctx
// grid: (SEQ, HV), 128 threads
// ---------------------------------------------------------------------------
__global__ void __launch_bounds__(128) rms_gate_kernel(
    const float* __restrict__ ctx, const float* __restrict__ gate,
    const float* __restrict__ rms_w, float* __restrict__ out)
{
    const int t = blockIdx.x;
    const int h = blockIdx.y;
    const int tid = threadIdx.x;
    size_t idx = (size_t)t * DOVG + h * 128 + tid;
    float v = ctx[idx];
    float ss = v * v;
#pragma unroll
    for (int m = 16; m; m >>= 1) ss += __shfl_xor_sync(0xffffffffu, ss, m);
    __shared__ float sw[4];
    if ((tid & 31) == 0) sw[tid >> 5] = ss;
    __syncthreads();
    float tot = sw[0] + sw[1] + sw[2] + sw[3];
    float sc = rsqrtf(tot * (1.f / 128.f) + 1e-6f);
    out[idx] = v * sc * rms_w[tid] * gate[idx];
}

// ---------------------------------------------------------------------------
extern "C" void kernel_launch(void* const* d_in, const int* in_sizes, int n_in,
                              void* d_out, int out_size)
{
    const float* x       = (const float*)d_in[0];
    const float* w_qkv   = (const float*)d_in[1];
    const float* w_gate  = (const float*)d_in[2];
    const float* w_beta  = (const float*)d_in[3];
    const float* w_alpha = (const float*)d_in[4];
    const float* log_A   = (const float*)d_in[5];
    const float* dt_bias = (const float*)d_in[6];
    const float* conv_w  = (const float*)d_in[7];
    const float* rms_w   = (const float*)d_in[8];
    const float* w_out   = (const float*)d_in[9];
    float* out = (float*)d_out;

    float *qkv_pre, *qkv, *gate, *ctx, *gctx, *beta, *alpha;
    cudaGetSymbolAddress((void**)&qkv_pre, g_qkv_pre);
    cudaGetSymbolAddress((void**)&qkv,     g_qkv);
    cudaGetSymbolAddress((void**)&gate,    g_gate);
    cudaGetSymbolAddress((void**)&ctx,     g_ctx);
    cudaGetSymbolAddress((void**)&gctx,    g_gctx);
    cudaGetSymbolAddress((void**)&beta,    g_beta);
    cudaGetSymbolAddress((void**)&alpha,   g_alpha);

    // 1) big projections
    sgemm_nt<<<dim3(FUSEDC / 128, SEQ / 128), 256>>>(x, w_qkv, qkv_pre, SEQ, FUSEDC, DIN, 0);
    sgemm_nt<<<dim3(DOVG / 128, SEQ / 128), 256>>>(x, w_gate, gate, SEQ, DOVG, DIN, 1);

    // 2) beta / alpha
    beta_alpha_kernel<<<SEQ, 256>>>(x, w_beta, w_alpha, log_A, dt_bias, beta, alpha);

    // 3) causal depthwise conv + silu
    conv_silu_kernel<<<(SEQ * FUSEDC) / 256, 256>>>(qkv_pre, conv_w, qkv);

    // 4) l2-normalize q and k (q also scaled by DK^-0.5)
    l2norm_kernel<<<dim3(SEQ, 16), 128>>>(qkv);

    // 5) gated delta-rule scan
    scan_kernel<<<128, 256>>>(qkv, beta, alpha, ctx);

    // 6) rms norm * rms_w * gate
    rms_gate_kernel<<<dim3(SEQ, HV), 128>>>(ctx, gate, rms_w, gctx);

    // 7) output projection
    sgemm_nt<<<dim3(DOVG / 128, SEQ / 128), 256>>>(gctx, w_out, out, SEQ, DOVG, DIN, 0);
}

// round 3
// speedup vs baseline: 2.5998x; 2.5998x over previous
#include <cuda_runtime.h>
#include <cuda_bf16.h>
#include <math.h>
#include <stdint.h>

// ---------------------------------------------------------------------------
// FusedGatedDeltaNet: B=1, S=1024, D_IN=2048, H_QK=8, H_V=16, DK=DV=128,
// KCONV=4, FUSED=4096, D_OUT=1024, D_OUT_VG=2048
// Big GEMMs via mma.sync bf16 (m16n8k16) with 2-term hi/lo split, 3 passes.
// ---------------------------------------------------------------------------

#define SEQ    1024
#define DIN    2048
#define FUSEDC 4096
#define HQK    8
#define HV     16
#define DOVG   2048
#define GK     2048

// ------------------------- scratch (static, no alloc) ----------------------
__device__ float g_qkv_pre[SEQ * FUSEDC];
__device__ float g_qkv[SEQ * FUSEDC];
__device__ float g_gate[SEQ * DOVG];
__device__ float g_ctx[SEQ * DOVG];
__device__ float g_beta[HV * SEQ];
__device__ float g_alpha[HV * SEQ];

__device__ __nv_bfloat16 g_x_hi[SEQ * DIN],       g_x_lo[SEQ * DIN];
__device__ __nv_bfloat16 g_wqkv_hi[FUSEDC * DIN], g_wqkv_lo[FUSEDC * DIN];
__device__ __nv_bfloat16 g_wg_hi[DOVG * DIN],     g_wg_lo[DOVG * DIN];
__device__ __nv_bfloat16 g_wo_hi[DOVG * DIN],     g_wo_lo[DOVG * DIN];
__device__ __nv_bfloat16 g_gctx_hi[SEQ * DOVG],   g_gctx_lo[SEQ * DOVG];

// ------------------------- helpers -----------------------------------------
__device__ __forceinline__ uint32_t smem_u32(const void* p) {
    uint32_t a;
    asm("{ .reg .u64 t; cvta.to.shared.u64 t, %1; cvt.u32.u64 %0, t; }"
        : "=r"(a) : "l"(p));
    return a;
}
__device__ __forceinline__ void cp_async16(uint32_t dst, const void* src) {
    asm volatile("cp.async.cg.shared.global [%0], [%1], 16;"
                 :: "r"(dst), "l"(src));
}
__device__ __forceinline__ void cp_commit() {
    asm volatile("cp.async.commit_group;");
}
__device__ __forceinline__ void ldmatrix_x4(uint32_t* r, uint32_t addr) {
    asm volatile("ldmatrix.sync.aligned.m8n8.x4.shared.b16 {%0,%1,%2,%3}, [%4];"
                 : "=r"(r[0]), "=r"(r[1]), "=r"(r[2]), "=r"(r[3]) : "r"(addr));
}
__device__ __forceinline__ void ldmatrix_x2(uint32_t* r, uint32_t addr) {
    asm volatile("ldmatrix.sync.aligned.m8n8.x2.shared.b16 {%0,%1}, [%2];"
                 : "=r"(r[0]), "=r"(r[1]) : "r"(addr));
}
__device__ __forceinline__ void mma16816(float* d, const uint32_t* a, const uint32_t* b) {
    asm volatile("mma.sync.aligned.m16n8k16.row.col.f32.bf16.bf16.f32 "
                 "{%0,%1,%2,%3}, {%4,%5,%6,%7}, {%8,%9}, {%0,%1,%2,%3};"
                 : "+f"(d[0]), "+f"(d[1]), "+f"(d[2]), "+f"(d[3])
                 : "r"(a[0]), "r"(a[1]), "r"(a[2]), "r"(a[3]),
                   "r"(b[0]), "r"(b[1]));
}

// ---------------------------------------------------------------------------
// 3-pass split-bf16 tensor-core GEMM:
//   C[1024, N] = A[1024, 2048] * B[N, 2048]^T   (fp32-equivalent precision)
// passes: A_hi*B_hi + A_hi*B_lo + A_lo*B_hi
// CTA tile 128x128, K-chunk 32 bf16, 8 warps (2m x 4n), warp tile 64x32.
// smem stride 40 bf16 (80B, 16B-aligned) -> conflict-free STS/ldmatrix.
// ---------------------------------------------------------------------------
#define SASTR 40
#define ABYTES (128 * SASTR * 2)
#define NCHUNK 192   // 3 passes x 64 chunks of K=32

__global__ void __launch_bounds__(256, 2) gemm3p(
    const __nv_bfloat16* __restrict__ Ahi, const __nv_bfloat16* __restrict__ Alo,
    const __nv_bfloat16* __restrict__ Bhi, const __nv_bfloat16* __restrict__ Blo,
    float* __restrict__ C, int N, int epi)
{
    __shared__ __align__(16) __nv_bfloat16 sA[2][128][SASTR];
    __shared__ __align__(16) __nv_bfloat16 sB[2][128][SASTR];

    const int tid  = threadIdx.x;
    const int lane = tid & 31;
    const int wrp  = tid >> 5;
    const int wm   = wrp >> 2;       // 0..1
    const int wn   = wrp & 3;        // 0..3
    const int bm   = blockIdx.y * 128;
    const int bn   = blockIdx.x * 128;

    const uint32_t sAb = smem_u32(&sA[0][0][0]);
    const uint32_t sBb = smem_u32(&sB[0][0][0]);

    // per-thread global load mapping: 2 iters x (A 16B + B 16B)
    const int ld_row = tid >> 2;           // 0..63  (+64 on iter 1)
    const int ld_seg = (tid & 3) * 8;      // bf16 offset within 32-col chunk

    // ldmatrix address components
    const int a_row = wm * 64 + (lane & 15);
    const int a_ko  = (lane >> 4) * 8;
    const uint32_t a_addr0 = sAb + (uint32_t)(a_row * SASTR + a_ko) * 2;
    const int b_row = wn * 32 + (lane & 7);
    const int b_ko  = ((lane >> 3) & 1) * 8;
    const uint32_t b_addr0 = sBb + (uint32_t)(b_row * SASTR + b_ko) * 2;

    float acc[4][4][4];
#pragma unroll
    for (int i = 0; i < 4; ++i)
#pragma unroll
        for (int j = 0; j < 4; ++j)
#pragma unroll
            for (int q = 0; q < 4; ++q) acc[i][j][q] = 0.f;

    // ---- chunk issue lambda (manual) ----
    // pass p: A from (p==2 ? Alo : Ahi), B from (p==1 ? Blo : Bhi)
    // chunk c: kc = (c & 63) * 32
    {
        // prologue: chunk 0 -> buf 0
        const __nv_bfloat16* Ap = Ahi;
        const __nv_bfloat16* Bp = Bhi;
#pragma unroll
        for (int it = 0; it < 2; ++it) {
            int row = ld_row + it * 64;
            cp_async16(sAb + (uint32_t)(row * SASTR + ld_seg) * 2,
                       Ap + (size_t)(bm + row) * GK + ld_seg);
            cp_async16(sBb + (uint32_t)(row * SASTR + ld_seg) * 2,
                       Bp + (size_t)(bn + row) * GK + ld_seg);
        }
        cp_commit();
    }

    for (int c = 0; c < NCHUNK; ++c) {
        const int buf = c & 1;
        if (c + 1 < NCHUNK) {
            const int cn = c + 1;
            const int p  = cn >> 6;
            const int kc = (cn & 63) << 5;
            const __nv_bfloat16* Ap = (p == 2) ? Alo : Ahi;
            const __nv_bfloat16* Bp = (p == 1) ? Blo : Bhi;
            const uint32_t off = (uint32_t)(buf ^ 1) * ABYTES;
#pragma unroll
            for (int it = 0; it < 2; ++it) {
                int row = ld_row + it * 64;
                cp_async16(sAb + off + (uint32_t)(row * SASTR + ld_seg) * 2,
                           Ap + (size_t)(bm + row) * GK + kc + ld_seg);
                cp_async16(sBb + off + (uint32_t)(row * SASTR + ld_seg) * 2,
                           Bp + (size_t)(bn + row) * GK + kc + ld_seg);
            }
            cp_commit();
            asm volatile("cp.async.wait_group 1;");
        } else {
            asm volatile("cp.async.wait_group 0;");
        }
        __syncthreads();

        const uint32_t aoff = (uint32_t)buf * ABYTES;
#pragma unroll
        for (int ks = 0; ks < 2; ++ks) {
            uint32_t afr[4][4], bfr[4][2];
#pragma unroll
            for (int mt = 0; mt < 4; ++mt)
                ldmatrix_x4(afr[mt], a_addr0 + aoff + mt * (16 * SASTR * 2) + ks * 32);
#pragma unroll
            for (int nt = 0; nt < 4; ++nt)
                ldmatrix_x2(bfr[nt], b_addr0 + aoff + nt * (8 * SASTR * 2) + ks * 32);
#pragma unroll
            for (int mt = 0; mt < 4; ++mt)
#pragma unroll
                for (int nt = 0; nt < 4; ++nt)
                    mma16816(acc[mt][nt], afr[mt], bfr[nt]);
        }
        __syncthreads();
    }

    // ---- epilogue ----
#pragma unroll
    for (int mt = 0; mt < 4; ++mt) {
        int row0 = bm + wm * 64 + mt * 16 + (lane >> 2);
#pragma unroll
        for (int nt = 0; nt < 4; ++nt) {
            int col = bn + wn * 32 + nt * 8 + (lane & 3) * 2;
            float2 v0 = make_float2(acc[mt][nt][0], acc[mt][nt][1]);
            float2 v1 = make_float2(acc[mt][nt][2], acc[mt][nt][3]);
            if (epi == 1) {
                v0.x = v0.x / (1.f + expf(-v0.x));
                v0.y = v0.y / (1.f + expf(-v0.y));
                v1.x = v1.x / (1.f + expf(-v1.x));
                v1.y = v1.y / (1.f + expf(-v1.y));
            }
            *(float2*)(C + (size_t)row0 * N + col) = v0;
            *(float2*)(C + (size_t)(row0 + 8) * N + col) = v1;
        }
    }
}

// ---------------------------------------------------------------------------
// fp32 -> (bf16 hi, bf16 lo) split
// ---------------------------------------------------------------------------
__global__ void __launch_bounds__(256) split_bf16(
    const float* __restrict__ in, __nv_bfloat16* __restrict__ hi,
    __nv_bfloat16* __restrict__ lo, int n4)
{
    int i = blockIdx.x * 256 + threadIdx.x;
    if (i >= n4) return;
    float4 v = ((const float4*)in)[i];
    __nv_bfloat16 h0 = __float2bfloat16(v.x), h1 = __float2bfloat16(v.y);
    __nv_bfloat16 h2 = __float2bfloat16(v.z), h3 = __float2bfloat16(v.w);
    __nv_bfloat16 l0 = __float2bfloat16(v.x - __bfloat162float(h0));
    __nv_bfloat16 l1 = __float2bfloat16(v.y - __bfloat162float(h1));
    __nv_bfloat16 l2 = __float2bfloat16(v.z - __bfloat162float(h2));
    __nv_bfloat16 l3 = __float2bfloat16(v.w - __bfloat162float(h3));
    ((__nv_bfloat162*)hi)[i * 2 + 0] = __halves2bfloat162(h0, h1);
    ((__nv_bfloat162*)hi)[i * 2 + 1] = __halves2bfloat162(h2, h3);
    ((__nv_bfloat162*)lo)[i * 2 + 0] = __halves2bfloat162(l0, l1);
    ((__nv_bfloat162*)lo)[i * 2 + 1] = __halves2bfloat162(l2, l3);
}

// ---------------------------------------------------------------------------
// beta / alpha projections (x row staged in smem)
// ---------------------------------------------------------------------------
__global__ void __launch_bounds__(256) beta_alpha_kernel(
    const float* __restrict__ x, const float* __restrict__ w_beta,
    const float* __restrict__ w_alpha, const float* __restrict__ log_A,
    const float* __restrict__ dt_bias,
    float* __restrict__ beta, float* __restrict__ alpha)
{
    __shared__ float sx[DIN];
    const int t = blockIdx.x;
    const int warp = threadIdx.x >> 5;
    const int lane = threadIdx.x & 31;
    for (int i = threadIdx.x; i < DIN / 4; i += 256)
        ((float4*)sx)[i] = ((const float4*)(x + (size_t)t * DIN))[i];
    __syncthreads();

#pragma unroll
    for (int d = 0; d < 4; ++d) {
        int idx = warp + (d << 3);
        const float* w = (idx < 16) ? (w_beta + (size_t)idx * DIN)
                                    : (w_alpha + (size_t)(idx - 16) * DIN);
        float s = 0.f;
        for (int k = lane; k < DIN; k += 32) s = fmaf(sx[k], w[k], s);
#pragma unroll
        for (int m = 16; m; m >>= 1) s += __shfl_xor_sync(0xffffffffu, s, m);
        if (lane == 0) {
            if (idx < 16) {
                beta[idx * SEQ + t] = 1.f / (1.f + expf(-s));
            } else {
                int h = idx - 16;
                float z = s + dt_bias[h];
                float sp = (z > 20.f) ? z : log1pf(expf(z));
                alpha[h * SEQ + t] = expf(-expf(log_A[h]) * sp);
            }
        }
    }
}

// ---------------------------------------------------------------------------
// causal depthwise conv1d (K=4) + SiLU
// ---------------------------------------------------------------------------
__global__ void __launch_bounds__(256) conv_silu_kernel(
    const float* __restrict__ in, const float* __restrict__ w,
    float* __restrict__ out)
{
    int idx = blockIdx.x * 256 + threadIdx.x;
    int c = idx & (FUSEDC - 1);
    int t = idx >> 12;
    float4 wc = *(const float4*)(w + c * 4);
    float s = wc.w * in[(size_t)t * FUSEDC + c];
    if (t >= 1) s = fmaf(wc.z, in[(size_t)(t - 1) * FUSEDC + c], s);
    if (t >= 2) s = fmaf(wc.y, in[(size_t)(t - 2) * FUSEDC + c], s);
    if (t >= 3) s = fmaf(wc.x, in[(size_t)(t - 3) * FUSEDC + c], s);
    out[idx] = s / (1.f + expf(-s));
}

// ---------------------------------------------------------------------------
// L2-normalize q/k heads in place (q also scaled by DK^-0.5)
// ---------------------------------------------------------------------------
__global__ void __launch_bounds__(128) l2norm_kernel(float* __restrict__ qkv)
{
    const int t = blockIdx.x;
    const int g = blockIdx.y;
    const int tid = threadIdx.x;
    size_t base = (size_t)t * FUSEDC + g * 128;
    float v = qkv[base + tid];
    float ss = v * v;
#pragma unroll
    for (int m = 16; m; m >>= 1) ss += __shfl_xor_sync(0xffffffffu, ss, m);
    __shared__ float sw[4];
    if ((tid & 31) == 0) sw[tid >> 5] = ss;
    __syncthreads();
    float tot = sw[0] + sw[1] + sw[2] + sw[3];
    float sc = rsqrtf(tot + 1e-6f);
    if (g < 8) sc *= 0.08838834764831845f;
    qkv[base + tid] = v * sc;
}

// ---------------------------------------------------------------------------
// Gated delta-rule scan (16 heads x 8 column blocks = 128 CTAs, 256 threads)
// ---------------------------------------------------------------------------
#define TSCHUNK 32
__global__ void __launch_bounds__(256) scan_kernel(
    const float* __restrict__ qkv, const float* __restrict__ beta,
    const float* __restrict__ alpha, float* __restrict__ ctx)
{
    const int h  = blockIdx.x >> 3;
    const int cb = blockIdx.x & 7;
    const int hq = h >> 1;
    const int tid  = threadIdx.x;
    const int lane = tid & 31;
    const int warp = tid >> 5;
    const int j    = (warp << 1) | (lane >> 4);
    const int sub  = lane & 15;

    __shared__ float sk[TSCHUNK][128];
    __shared__ float sq[TSCHUNK][128];
    __shared__ float sv[TSCHUNK][16];
    __shared__ float sb[TSCHUNK], sa[TSCHUNK];

    float S[8];
#pragma unroll
    for (int i = 0; i < 8; ++i) S[i] = 0.f;

    const float* qbase = qkv + hq * 128;
    const float* kbase = qkv + 1024 + hq * 128;
    const float* vbase = qkv + 2048 + h * 128 + cb * 16;
    float* obase = ctx + h * 128 + cb * 16 + j;

    for (int t0 = 0; t0 < SEQ; t0 += TSCHUNK) {
        __syncthreads();
#pragma unroll
        for (int u = 0; u < (TSCHUNK * 128) / 256; ++u) {
            int lin = tid + u * 256;
            int tt = lin >> 7, d = lin & 127;
            size_t off = (size_t)(t0 + tt) * FUSEDC + d;
            sq[tt][d] = qbase[off];
            sk[tt][d] = kbase[off];
        }
#pragma unroll
        for (int u = 0; u < 2; ++u) {
            int lin = tid + u * 256;
            int tt = lin >> 4, jj = lin & 15;
            sv[tt][jj] = vbase[(size_t)(t0 + tt) * FUSEDC + jj];
        }
        if (tid < TSCHUNK) {
            sb[tid] = beta[h * SEQ + t0 + tid];
            sa[tid] = alpha[h * SEQ + t0 + tid];
        }
        __syncthreads();

        for (int tt = 0; tt < TSCHUNK; ++tt) {
            float a = sa[tt], b = sb[tt];
            float kr[8], qr[8];
#pragma unroll
            for (int i = 0; i < 8; ++i) {
                kr[i] = sk[tt][sub + (i << 4)];
                qr[i] = sq[tt][sub + (i << 4)];
            }
            float kv0 = 0.f, kv1 = 0.f;
#pragma unroll
            for (int i = 0; i < 8; i += 2) {
                kv0 = fmaf(kr[i],     S[i],     kv0);
                kv1 = fmaf(kr[i + 1], S[i + 1], kv1);
            }
            float kv = kv0 + kv1;
            kv += __shfl_xor_sync(0xffffffffu, kv, 1);
            kv += __shfl_xor_sync(0xffffffffu, kv, 2);
            kv += __shfl_xor_sync(0xffffffffu, kv, 4);
            kv += __shfl_xor_sync(0xffffffffu, kv, 8);
            float uval = (sv[tt][j] - a * kv) * b;
            float o0 = 0.f, o1 = 0.f;
#pragma unroll
            for (int i = 0; i < 8; ++i)
                S[i] = fmaf(a, S[i], kr[i] * uval);
#pragma unroll
            for (int i = 0; i < 8; i += 2) {
                o0 = fmaf(qr[i],     S[i],     o0);
                o1 = fmaf(qr[i + 1], S[i + 1], o1);
            }
            float o = o0 + o1;
            o += __shfl_xor_sync(0xffffffffu, o, 1);
            o += __shfl_xor_sync(0xffffffffu, o, 2);
            o += __shfl_xor_sync(0xffffffffu, o, 4);
            o += __shfl_xor_sync(0xffffffffu, o, 8);
            if (sub == 0) obase[(size_t)(t0 + tt) * DOVG] = o;
        }
    }
}

// ---------------------------------------------------------------------------
// rms_norm(ctx) * rms_w * gate -> split bf16 (hi/lo) for final GEMM
// ---------------------------------------------------------------------------
__global__ void __launch_bounds__(128) rms_gate_kernel(
    const float* __restrict__ ctx, const float* __restrict__ gate,
    const float* __restrict__ rms_w,
    __nv_bfloat16* __restrict__ ghi, __nv_bfloat16* __restrict__ glo)
{
    const int t = blockIdx.x;
    const int h = blockIdx.y;
    const int tid = threadIdx.x;
    size_t idx = (size_t)t * DOVG + h * 128 + tid;
    float v = ctx[idx];
    float ss = v * v;
#pragma unroll
    for (int m = 16; m; m >>= 1) ss += __shfl_xor_sync(0xffffffffu, ss, m);
    __shared__ float sw[4];
    if ((tid & 31) == 0) sw[tid >> 5] = ss;
    __syncthreads();
    float tot = sw[0] + sw[1] + sw[2] + sw[3];
    float sc = rsqrtf(tot * (1.f / 128.f) + 1e-6f);
    float r = v * sc * rms_w[tid] * gate[idx];
    __nv_bfloat16 hh = __float2bfloat16(r);
    ghi[idx] = hh;
    glo[idx] = __float2bfloat16(r - __bfloat162float(hh));
}

// ---------------------------------------------------------------------------
extern "C" void kernel_launch(void* const* d_in, const int* in_sizes, int n_in,
                              void* d_out, int out_size)
{
    const float* x       = (const float*)d_in[0];
    const float* w_qkv   = (const float*)d_in[1];
    const float* w_gate  = (const float*)d_in[2];
    const float* w_beta  = (const float*)d_in[3];
    const float* w_alpha = (const float*)d_in[4];
    const float* log_A   = (const float*)d_in[5];
    const float* dt_bias = (const float*)d_in[6];
    const float* conv_w  = (const float*)d_in[7];
    const float* rms_w   = (const float*)d_in[8];
    const float* w_out   = (const float*)d_in[9];
    float* out = (float*)d_out;

    float *qkv_pre, *qkv, *gate, *ctx, *beta, *alpha;
    __nv_bfloat16 *x_hi, *x_lo, *wqkv_hi, *wqkv_lo, *wg_hi, *wg_lo,
                  *wo_hi, *wo_lo, *gctx_hi, *gctx_lo;
    cudaGetSymbolAddress((void**)&qkv_pre, g_qkv_pre);
    cudaGetSymbolAddress((void**)&qkv,     g_qkv);
    cudaGetSymbolAddress((void**)&gate,    g_gate);
    cudaGetSymbolAddress((void**)&ctx,     g_ctx);
    cudaGetSymbolAddress((void**)&beta,    g_beta);
    cudaGetSymbolAddress((void**)&alpha,   g_alpha);
    cudaGetSymbolAddress((void**)&x_hi,    g_x_hi);
    cudaGetSymbolAddress((void**)&x_lo,    g_x_lo);
    cudaGetSymbolAddress((void**)&wqkv_hi, g_wqkv_hi);
    cudaGetSymbolAddress((void**)&wqkv_lo, g_wqkv_lo);
    cudaGetSymbolAddress((void**)&wg_hi,   g_wg_hi);
    cudaGetSymbolAddress((void**)&wg_lo,   g_wg_lo);
    cudaGetSymbolAddress((void**)&wo_hi,   g_wo_hi);
    cudaGetSymbolAddress((void**)&wo_lo,   g_wo_lo);
    cudaGetSymbolAddress((void**)&gctx_hi, g_gctx_hi);
    cudaGetSymbolAddress((void**)&gctx_lo, g_gctx_lo);

    // 0) precision splits
    split_bf16<<<(SEQ * DIN / 4 + 255) / 256, 256>>>(x, x_hi, x_lo, SEQ * DIN / 4);
    split_bf16<<<(FUSEDC * DIN / 4 + 255) / 256, 256>>>(w_qkv, wqkv_hi, wqkv_lo, FUSEDC * DIN / 4);
    split_bf16<<<(DOVG * DIN / 4 + 255) / 256, 256>>>(w_gate, wg_hi, wg_lo, DOVG * DIN / 4);
    split_bf16<<<(DOVG * DIN / 4 + 255) / 256, 256>>>(w_out, wo_hi, wo_lo, DOVG * DIN / 4);

    // 1) big projections on tensor cores (legacy HMMA path)
    gemm3p<<<dim3(FUSEDC / 128, SEQ / 128), 256>>>(x_hi, x_lo, wqkv_hi, wqkv_lo,
                                                   qkv_pre, FUSEDC, 0);
    gemm3p<<<dim3(DOVG / 128, SEQ / 128), 256>>>(x_hi, x_lo, wg_hi, wg_lo,
                                                 gate, DOVG, 1);

    // 2) beta / alpha
    beta_alpha_kernel<<<SEQ, 256>>>(x, w_beta, w_alpha, log_A, dt_bias, beta, alpha);

    // 3) causal depthwise conv + silu
    conv_silu_kernel<<<(SEQ * FUSEDC) / 256, 256>>>(qkv_pre, conv_w, qkv);

    // 4) l2-normalize q/k
    l2norm_kernel<<<dim3(SEQ, 16), 128>>>(qkv);

    // 5) gated delta-rule scan
    scan_kernel<<<128, 256>>>(qkv, beta, alpha, ctx);

    // 6) rms norm * gate -> split bf16
    rms_gate_kernel<<<dim3(SEQ, HV), 128>>>(ctx, gate, rms_w, gctx_hi, gctx_lo);

    // 7) output projection
    gemm3p<<<dim3(DOVG / 128, SEQ / 128), 256>>>(gctx_hi, gctx_lo, wo_hi, wo_lo,
                                                 out, DOVG, 0);
}

// round 4
// speedup vs baseline: 2.8822x; 1.1086x over previous
#include <cuda_runtime.h>
#include <cuda_bf16.h>
#include <math.h>
#include <stdint.h>

// ---------------------------------------------------------------------------
// FusedGatedDeltaNet: B=1, S=1024, D_IN=2048, H_QK=8, H_V=16, DK=DV=128,
// KCONV=4, FUSED=4096, D_OUT=1024, D_OUT_VG=2048
// GEMMs: mma.sync bf16 m16n8k16, 2-term hi/lo split, 3 passes, 4-stage pipeline
// ---------------------------------------------------------------------------

#define SEQ    1024
#define DIN    2048
#define FUSEDC 4096
#define HV     16
#define DOVG   2048
#define GK     2048

// ------------------------- scratch (static, no alloc) ----------------------
__device__ float g_qkv_pre[SEQ * FUSEDC];
__device__ float g_qkv[SEQ * FUSEDC];
__device__ float g_gate[SEQ * DOVG];
__device__ float g_ctx[SEQ * DOVG];
__device__ float g_beta[HV * SEQ];
__device__ float g_alpha[HV * SEQ];

__device__ __nv_bfloat16 g_x_hi[SEQ * DIN],       g_x_lo[SEQ * DIN];
__device__ __nv_bfloat16 g_wqkv_hi[FUSEDC * DIN], g_wqkv_lo[FUSEDC * DIN];
__device__ __nv_bfloat16 g_wg_hi[DOVG * DIN],     g_wg_lo[DOVG * DIN];
__device__ __nv_bfloat16 g_wo_hi[DOVG * DIN],     g_wo_lo[DOVG * DIN];
__device__ __nv_bfloat16 g_gctx_hi[SEQ * DOVG],   g_gctx_lo[SEQ * DOVG];

// ------------------------- helpers -----------------------------------------
__device__ __forceinline__ uint32_t smem_u32(const void* p) {
    uint32_t a;
    asm("{ .reg .u64 t; cvta.to.shared.u64 t, %1; cvt.u32.u64 %0, t; }"
        : "=r"(a) : "l"(p));
    return a;
}
__device__ __forceinline__ void cp_async16(uint32_t dst, const void* src) {
    asm volatile("cp.async.cg.shared.global [%0], [%1], 16;"
                 :: "r"(dst), "l"(src));
}
__device__ __forceinline__ void ldmatrix_x4(uint32_t* r, uint32_t addr) {
    asm volatile("ldmatrix.sync.aligned.m8n8.x4.shared.b16 {%0,%1,%2,%3}, [%4];"
                 : "=r"(r[0]), "=r"(r[1]), "=r"(r[2]), "=r"(r[3]) : "r"(addr));
}
__device__ __forceinline__ void ldmatrix_x2(uint32_t* r, uint32_t addr) {
    asm volatile("ldmatrix.sync.aligned.m8n8.x2.shared.b16 {%0,%1}, [%2];"
                 : "=r"(r[0]), "=r"(r[1]) : "r"(addr));
}
__device__ __forceinline__ void mma16816(float* d, const uint32_t* a, const uint32_t* b) {
    asm volatile("mma.sync.aligned.m16n8k16.row.col.f32.bf16.bf16.f32 "
                 "{%0,%1,%2,%3}, {%4,%5,%6,%7}, {%8,%9}, {%0,%1,%2,%3};"
                 : "+f"(d[0]), "+f"(d[1]), "+f"(d[2]), "+f"(d[3])
                 : "r"(a[0]), "r"(a[1]), "r"(a[2]), "r"(a[3]),
                   "r"(b[0]), "r"(b[1]));
}

// ---------------------------------------------------------------------------
// 3-pass split-bf16 tensor-core GEMM, 4-stage cp.async pipeline.
//   C[1024, N] = A[1024, 2048] * B[N, 2048]^T   (fp32-equivalent)
// passes: A_hi*B_hi + A_hi*B_lo + A_lo*B_hi
// CTA tile 128x128, K-chunk 32, 8 warps (2m x 4n), warp tile 64x32.
// Column-merged: blocks with bn >= N1 use the second B/C (epi2).
// smem stride 40 bf16 -> conflict-free STS.128 / ldmatrix.
// ---------------------------------------------------------------------------
#define SASTR   40
#define STAGEB  20480            // bytes per stage (A 10240 + B 10240)
#define STAGES  4
#define GSMEM   (STAGES * STAGEB)
#define NCHUNK  192              // 3 passes x 64 chunks of K=32

__global__ void __launch_bounds__(256, 2) gemm3p(
    const __nv_bfloat16* __restrict__ Ahi, const __nv_bfloat16* __restrict__ Alo,
    const __nv_bfloat16* __restrict__ B1hi, const __nv_bfloat16* __restrict__ B1lo,
    const __nv_bfloat16* __restrict__ B2hi, const __nv_bfloat16* __restrict__ B2lo,
    float* __restrict__ C1, float* __restrict__ C2,
    int N1, int N2, int epi1, int epi2)
{
    extern __shared__ char dynsmem[];
    const uint32_t sb = smem_u32(dynsmem);

    const int tid  = threadIdx.x;
    const int lane = tid & 31;
    const int wrp  = tid >> 5;
    const int wm   = wrp >> 2;
    const int wn   = wrp & 3;
    const int bm   = blockIdx.y * 128;

    int bn = blockIdx.x * 128;
    const __nv_bfloat16* BH;
    const __nv_bfloat16* BL;
    float* Cp;
    int N, epi;
    if (bn < N1) { BH = B1hi; BL = B1lo; Cp = C1; N = N1; epi = epi1; }
    else { bn -= N1; BH = B2hi; BL = B2lo; Cp = C2; N = N2; epi = epi2; }

    // global->smem mapping: 2 iters x (A 16B + B 16B) per thread
    const int ld_row = tid >> 2;
    const int ld_seg = (tid & 3) * 8;
    const uint32_t st_off = (uint32_t)(ld_row * SASTR + ld_seg) * 2;

    // ldmatrix address components
    const int a_row = wm * 64 + (lane & 15);
    const int a_ko  = (lane >> 4) * 8;
    const uint32_t a_addr0 = sb + (uint32_t)(a_row * SASTR + a_ko) * 2;
    const int b_row = wn * 32 + (lane & 7);
    const int b_ko  = ((lane >> 3) & 1) * 8;
    const uint32_t b_addr0 = sb + 10240 + (uint32_t)(b_row * SASTR + b_ko) * 2;

    float acc[4][4][4];
#pragma unroll
    for (int i = 0; i < 4; ++i)
#pragma unroll
        for (int j = 0; j < 4; ++j)
#pragma unroll
            for (int q = 0; q < 4; ++q) acc[i][j][q] = 0.f;

    // prologue: issue chunks 0..STAGES-2
#pragma unroll
    for (int s = 0; s < STAGES - 1; ++s) {
        const int p  = s >> 6;
        const int kc = (s & 63) << 5;
        const __nv_bfloat16* Ap = (p == 2) ? Alo : Ahi;
        const __nv_bfloat16* Bp = (p == 1) ? BL : BH;
        const uint32_t so = sb + (uint32_t)s * STAGEB;
#pragma unroll
        for (int it = 0; it < 2; ++it) {
            int row = ld_row + it * 64;
            uint32_t o = st_off + (uint32_t)(it * 64 * SASTR) * 2;
            cp_async16(so + o,         Ap + (size_t)(bm + row) * GK + kc + ld_seg);
            cp_async16(so + 10240 + o, Bp + (size_t)(bn + row) * GK + kc + ld_seg);
        }
        asm volatile("cp.async.commit_group;");
    }

    for (int c = 0; c < NCHUNK; ++c) {
        asm volatile("cp.async.wait_group %0;" :: "n"(STAGES - 2));
        __syncthreads();

        const uint32_t soff = (uint32_t)(c & (STAGES - 1)) * STAGEB;
#pragma unroll
        for (int ks = 0; ks < 2; ++ks) {
            uint32_t afr[4][4], bfr[4][2];
#pragma unroll
            for (int mt = 0; mt < 4; ++mt)
                ldmatrix_x4(afr[mt], a_addr0 + soff + mt * (16 * SASTR * 2) + ks * 32);
#pragma unroll
            for (int nt = 0; nt < 4; ++nt)
                ldmatrix_x2(bfr[nt], b_addr0 + soff + nt * (8 * SASTR * 2) + ks * 32);
#pragma unroll
            for (int mt = 0; mt < 4; ++mt)
#pragma unroll
                for (int nt = 0; nt < 4; ++nt)
                    mma16816(acc[mt][nt], afr[mt], bfr[nt]);
        }

        // issue chunk c+STAGES-1 into the stage just freed (consumed at iter c-1)
        const int cn = c + STAGES - 1;
        if (cn < NCHUNK) {
            const int p  = cn >> 6;
            const int kc = (cn & 63) << 5;
            const __nv_bfloat16* Ap = (p == 2) ? Alo : Ahi;
            const __nv_bfloat16* Bp = (p == 1) ? BL : BH;
            const uint32_t so = sb + (uint32_t)(cn & (STAGES - 1)) * STAGEB;
#pragma unroll
            for (int it = 0; it < 2; ++it) {
                int row = ld_row + it * 64;
                uint32_t o = st_off + (uint32_t)(it * 64 * SASTR) * 2;
                cp_async16(so + o,         Ap + (size_t)(bm + row) * GK + kc + ld_seg);
                cp_async16(so + 10240 + o, Bp + (size_t)(bn + row) * GK + kc + ld_seg);
            }
        }
        asm volatile("cp.async.commit_group;");
    }

    // ---- epilogue ----
#pragma unroll
    for (int mt = 0; mt < 4; ++mt) {
        int row0 = bm + wm * 64 + mt * 16 + (lane >> 2);
#pragma unroll
        for (int nt = 0; nt < 4; ++nt) {
            int col = bn + wn * 32 + nt * 8 + (lane & 3) * 2;
            float2 v0 = make_float2(acc[mt][nt][0], acc[mt][nt][1]);
            float2 v1 = make_float2(acc[mt][nt][2], acc[mt][nt][3]);
            if (epi == 1) {
                v0.x = v0.x / (1.f + expf(-v0.x));
                v0.y = v0.y / (1.f + expf(-v0.y));
                v1.x = v1.x / (1.f + expf(-v1.x));
                v1.y = v1.y / (1.f + expf(-v1.y));
            }
            *(float2*)(Cp + (size_t)row0 * N + col) = v0;
            *(float2*)(Cp + (size_t)(row0 + 8) * N + col) = v1;
        }
    }
}

// ---------------------------------------------------------------------------
// fp32 -> (bf16 hi, bf16 lo) split
// ---------------------------------------------------------------------------
__global__ void __launch_bounds__(256) split_bf16(
    const float* __restrict__ in, __nv_bfloat16* __restrict__ hi,
    __nv_bfloat16* __restrict__ lo, int n4)
{
    int i = blockIdx.x * 256 + threadIdx.x;
    if (i >= n4) return;
    float4 v = ((const float4*)in)[i];
    __nv_bfloat16 h0 = __float2bfloat16(v.x), h1 = __float2bfloat16(v.y);
    __nv_bfloat16 h2 = __float2bfloat16(v.z), h3 = __float2bfloat16(v.w);
    __nv_bfloat16 l0 = __float2bfloat16(v.x - __bfloat162float(h0));
    __nv_bfloat16 l1 = __float2bfloat16(v.y - __bfloat162float(h1));
    __nv_bfloat16 l2 = __float2bfloat16(v.z - __bfloat162float(h2));
    __nv_bfloat16 l3 = __float2bfloat16(v.w - __bfloat162float(h3));
    ((__nv_bfloat162*)hi)[i * 2 + 0] = __halves2bfloat162(h0, h1);
    ((__nv_bfloat162*)hi)[i * 2 + 1] = __halves2bfloat162(h2, h3);
    ((__nv_bfloat162*)lo)[i * 2 + 0] = __halves2bfloat162(l0, l1);
    ((__nv_bfloat162*)lo)[i * 2 + 1] = __halves2bfloat162(l2, l3);
}

// ---------------------------------------------------------------------------
// beta / alpha projections (x row staged in smem)
// ---------------------------------------------------------------------------
__global__ void __launch_bounds__(256) beta_alpha_kernel(
    const float* __restrict__ x, const float* __restrict__ w_beta,
    const float* __restrict__ w_alpha, const float* __restrict__ log_A,
    const float* __restrict__ dt_bias,
    float* __restrict__ beta, float* __restrict__ alpha)
{
    __shared__ float sx[DIN];
    const int t = blockIdx.x;
    const int warp = threadIdx.x >> 5;
    const int lane = threadIdx.x & 31;
    for (int i = threadIdx.x; i < DIN / 4; i += 256)
        ((float4*)sx)[i] = ((const float4*)(x + (size_t)t * DIN))[i];
    __syncthreads();

#pragma unroll
    for (int d = 0; d < 4; ++d) {
        int idx = warp + (d << 3);
        const float* w = (idx < 16) ? (w_beta + (size_t)idx * DIN)
                                    : (w_alpha + (size_t)(idx - 16) * DIN);
        float s = 0.f;
        for (int k = lane; k < DIN; k += 32) s = fmaf(sx[k], w[k], s);
#pragma unroll
        for (int m = 16; m; m >>= 1) s += __shfl_xor_sync(0xffffffffu, s, m);
        if (lane == 0) {
            if (idx < 16) {
                beta[idx * SEQ + t] = 1.f / (1.f + expf(-s));
            } else {
                int h = idx - 16;
                float z = s + dt_bias[h];
                float sp = (z > 20.f) ? z : log1pf(expf(z));
                alpha[h * SEQ + t] = expf(-expf(log_A[h]) * sp);
            }
        }
    }
}

// ---------------------------------------------------------------------------
// causal depthwise conv1d (K=4) + SiLU + fused l2norm for q/k head blocks
// grid: (SEQ, 32 blocks of 128 channels), 128 threads
// blocks 0..7 = q heads, 8..15 = k heads (l2-normalized), 16..31 = v
// ---------------------------------------------------------------------------
__global__ void __launch_bounds__(128) conv_l2_kernel(
    const float* __restrict__ in, const float* __restrict__ w,
    float* __restrict__ out)
{
    const int t   = blockIdx.x;
    const int blk = blockIdx.y;
    const int tid = threadIdx.x;
    const int c   = blk * 128 + tid;

    float4 wc = *(const float4*)(w + c * 4);
    const float* col = in + c;
    float s = wc.w * col[(size_t)t * FUSEDC];
    if (t >= 1) s = fmaf(wc.z, col[(size_t)(t - 1) * FUSEDC], s);
    if (t >= 2) s = fmaf(wc.y, col[(size_t)(t - 2) * FUSEDC], s);
    if (t >= 3) s = fmaf(wc.x, col[(size_t)(t - 3) * FUSEDC], s);
    float v = s / (1.f + expf(-s));

    if (blk < 16) {
        float ss = v * v;
#pragma unroll
        for (int m = 16; m; m >>= 1) ss += __shfl_xor_sync(0xffffffffu, ss, m);
        __shared__ float sw[4];
        if ((tid & 31) == 0) sw[tid >> 5] = ss;
        __syncthreads();
        float tot = sw[0] + sw[1] + sw[2] + sw[3];
        float sc = rsqrtf(tot + 1e-6f);
        if (blk < 8) sc *= 0.08838834764831845f;   // q: fold DK^-0.5
        v *= sc;
    }
    out[(size_t)t * FUSEDC + c] = v;
}

// ---------------------------------------------------------------------------
// Gated delta-rule scan (16 heads x 8 column blocks = 128 CTAs, 256 threads)
// Thread owns contiguous rows sub*8 .. sub*8+7 of its column -> float4 LDS.
// ---------------------------------------------------------------------------
#define TSCHUNK 32
__global__ void __launch_bounds__(256) scan_kernel(
    const float* __restrict__ qkv, const float* __restrict__ beta,
    const float* __restrict__ alpha, float* __restrict__ ctx)
{
    const int h  = blockIdx.x >> 3;
    const int cb = blockIdx.x & 7;
    const int hq = h >> 1;
    const int tid  = threadIdx.x;
    const int lane = tid & 31;
    const int warp = tid >> 5;
    const int j    = (warp << 1) | (lane >> 4);
    const int sub  = lane & 15;

    __shared__ __align__(16) float sk[TSCHUNK][128];
    __shared__ __align__(16) float sq[TSCHUNK][128];
    __shared__ float sv[TSCHUNK][16];
    __shared__ float sb[TSCHUNK], sa[TSCHUNK];

    float S[8];
#pragma unroll
    for (int i = 0; i < 8; ++i) S[i] = 0.f;

    const float* qbase = qkv + hq * 128;
    const float* kbase = qkv + 1024 + hq * 128;
    const float* vbase = qkv + 2048 + h * 128 + cb * 16;
    float* obase = ctx + h * 128 + cb * 16 + j;

    for (int t0 = 0; t0 < SEQ; t0 += TSCHUNK) {
        __syncthreads();
#pragma unroll
        for (int u = 0; u < (TSCHUNK * 128) / 256; ++u) {
            int lin = tid + u * 256;
            int tt = lin >> 7, d = lin & 127;
            size_t off = (size_t)(t0 + tt) * FUSEDC + d;
            sq[tt][d] = qbase[off];
            sk[tt][d] = kbase[off];
        }
#pragma unroll
        for (int u = 0; u < 2; ++u) {
            int lin = tid + u * 256;
            int tt = lin >> 4, jj = lin & 15;
            sv[tt][jj] = vbase[(size_t)(t0 + tt) * FUSEDC + jj];
        }
        if (tid < TSCHUNK) {
            sb[tid] = beta[h * SEQ + t0 + tid];
            sa[tid] = alpha[h * SEQ + t0 + tid];
        }
        __syncthreads();

        for (int tt = 0; tt < TSCHUNK; ++tt) {
            float a = sa[tt], b = sb[tt];
            float kr[8], qr[8];
            *(float4*)(kr)     = *(const float4*)&sk[tt][sub * 8];
            *(float4*)(kr + 4) = *(const float4*)&sk[tt][sub * 8 + 4];
            *(float4*)(qr)     = *(const float4*)&sq[tt][sub * 8];
            *(float4*)(qr + 4) = *(const float4*)&sq[tt][sub * 8 + 4];

            float kv0 = 0.f, kv1 = 0.f;
#pragma unroll
            for (int i = 0; i < 8; i += 2) {
                kv0 = fmaf(kr[i],     S[i],     kv0);
                kv1 = fmaf(kr[i + 1], S[i + 1], kv1);
            }
            float kv = kv0 + kv1;
            kv += __shfl_xor_sync(0xffffffffu, kv, 1);
            kv += __shfl_xor_sync(0xffffffffu, kv, 2);
            kv += __shfl_xor_sync(0xffffffffu, kv, 4);
            kv += __shfl_xor_sync(0xffffffffu, kv, 8);
            float uval = (sv[tt][j] - a * kv) * b;
            float o0 = 0.f, o1 = 0.f;
#pragma unroll
            for (int i = 0; i < 8; ++i)
                S[i] = fmaf(a, S[i], kr[i] * uval);
#pragma unroll
            for (int i = 0; i < 8; i += 2) {
                o0 = fmaf(qr[i],     S[i],     o0);
                o1 = fmaf(qr[i + 1], S[i + 1], o1);
            }
            float o = o0 + o1;
            o += __shfl_xor_sync(0xffffffffu, o, 1);
            o += __shfl_xor_sync(0xffffffffu, o, 2);
            o += __shfl_xor_sync(0xffffffffu, o, 4);
            o += __shfl_xor_sync(0xffffffffu, o, 8);
            if (sub == 0) obase[(size_t)(t0 + tt) * DOVG] = o;
        }
    }
}

// ---------------------------------------------------------------------------
// rms_norm(ctx) * rms_w * gate -> split bf16 (hi/lo) for final GEMM
// ---------------------------------------------------------------------------
__global__ void __launch_bounds__(128) rms_gate_kernel(
    const float* __restrict__ ctx, const float* __restrict__ gate,
    const float* __restrict__ rms_w,
    __nv_bfloat16* __restrict__ ghi, __nv_bfloat16* __restrict__ glo)
{
    const int t = blockIdx.x;
    const int h = blockIdx.y;
    const int tid = threadIdx.x;
    size_t idx = (size_t)t * DOVG + h * 128 + tid;
    float v = ctx[idx];
    float ss = v * v;
#pragma unroll
    for (int m = 16; m; m >>= 1) ss += __shfl_xor_sync(0xffffffffu, ss, m);
    __shared__ float sw[4];
    if ((tid & 31) == 0) sw[tid >> 5] = ss;
    __syncthreads();
    float tot = sw[0] + sw[1] + sw[2] + sw[3];
    float sc = rsqrtf(tot * (1.f / 128.f) + 1e-6f);
    float r = v * sc * rms_w[tid] * gate[idx];
    __nv_bfloat16 hh = __float2bfloat16(r);
    ghi[idx] = hh;
    glo[idx] = __float2bfloat16(r - __bfloat162float(hh));
}

// ---------------------------------------------------------------------------
extern "C" void kernel_launch(void* const* d_in, const int* in_sizes, int n_in,
                              void* d_out, int out_size)
{
    const float* x       = (const float*)d_in[0];
    const float* w_qkv   = (const float*)d_in[1];
    const float* w_gate  = (const float*)d_in[2];
    const float* w_beta  = (const float*)d_in[3];
    const float* w_alpha = (const float*)d_in[4];
    const float* log_A   = (const float*)d_in[5];
    const float* dt_bias = (const float*)d_in[6];
    const float* conv_w  = (const float*)d_in[7];
    const float* rms_w   = (const float*)d_in[8];
    const float* w_out   = (const float*)d_in[9];
    float* out = (float*)d_out;

    float *qkv_pre, *qkv, *gate, *ctx, *beta, *alpha;
    __nv_bfloat16 *x_hi, *x_lo, *wqkv_hi, *wqkv_lo, *wg_hi, *wg_lo,
                  *wo_hi, *wo_lo, *gctx_hi, *gctx_lo;
    cudaGetSymbolAddress((void**)&qkv_pre, g_qkv_pre);
    cudaGetSymbolAddress((void**)&qkv,     g_qkv);
    cudaGetSymbolAddress((void**)&gate,    g_gate);
    cudaGetSymbolAddress((void**)&ctx,     g_ctx);
    cudaGetSymbolAddress((void**)&beta,    g_beta);
    cudaGetSymbolAddress((void**)&alpha,   g_alpha);
    cudaGetSymbolAddress((void**)&x_hi,    g_x_hi);
    cudaGetSymbolAddress((void**)&x_lo,    g_x_lo);
    cudaGetSymbolAddress((void**)&wqkv_hi, g_wqkv_hi);
    cudaGetSymbolAddress((void**)&wqkv_lo, g_wqkv_lo);
    cudaGetSymbolAddress((void**)&wg_hi,   g_wg_hi);
    cudaGetSymbolAddress((void**)&wg_lo,   g_wg_lo);
    cudaGetSymbolAddress((void**)&wo_hi,   g_wo_hi);
    cudaGetSymbolAddress((void**)&wo_lo,   g_wo_lo);
    cudaGetSymbolAddress((void**)&gctx_hi, g_gctx_hi);
    cudaGetSymbolAddress((void**)&gctx_lo, g_gctx_lo);

    cudaFuncSetAttribute(gemm3p, cudaFuncAttributeMaxDynamicSharedMemorySize, GSMEM);

    // 0) precision splits
    split_bf16<<<(SEQ * DIN / 4 + 255) / 256, 256>>>(x, x_hi, x_lo, SEQ * DIN / 4);
    split_bf16<<<(FUSEDC * DIN / 4 + 255) / 256, 256>>>(w_qkv, wqkv_hi, wqkv_lo, FUSEDC * DIN / 4);
    split_bf16<<<(DOVG * DIN / 4 + 255) / 256, 256>>>(w_gate, wg_hi, wg_lo, DOVG * DIN / 4);
    split_bf16<<<(DOVG * DIN / 4 + 255) / 256, 256>>>(w_out, wo_hi, wo_lo, DOVG * DIN / 4);

    // 1) fused qkv + gate projections (columns 0..4095 -> qkv, 4096..6143 -> gate+silu)
    gemm3p<<<dim3((FUSEDC + DOVG) / 128, SEQ / 128), 256, GSMEM>>>(
        x_hi, x_lo, wqkv_hi, wqkv_lo, wg_hi, wg_lo,
        qkv_pre, gate, FUSEDC, DOVG, 0, 1);

    // 2) beta / alpha
    beta_alpha_kernel<<<SEQ, 256>>>(x, w_beta, w_alpha, log_A, dt_bias, beta, alpha);

    // 3) causal depthwise conv + silu + fused l2norm on q/k
    conv_l2_kernel<<<dim3(SEQ, 32), 128>>>(qkv_pre, conv_w, qkv);

    // 4) gated delta-rule scan
    scan_kernel<<<128, 256>>>(qkv, beta, alpha, ctx);

    // 5) rms norm * gate -> split bf16
    rms_gate_kernel<<<dim3(SEQ, HV), 128>>>(ctx, gate, rms_w, gctx_hi, gctx_lo);

    // 6) output projection
    gemm3p<<<dim3(DOVG / 128, SEQ / 128), 256, GSMEM>>>(
        gctx_hi, gctx_lo, wo_hi, wo_lo, wo_hi, wo_lo,
        out, out, DOVG, DOVG, 0, 0);
}

// round 5
// speedup vs baseline: 3.3342x; 1.1568x over previous
#include <cuda_runtime.h>
#include <cuda_bf16.h>
#include <math.h>
#include <stdint.h>

// ---------------------------------------------------------------------------
// FusedGatedDeltaNet: B=1, S=1024, D_IN=2048, H_QK=8, H_V=16, DK=DV=128,
// KCONV=4, FUSED=4096, D_OUT=1024, D_OUT_VG=2048
// GEMMs: mma.sync bf16 m16n8k16, 3-pass hi/lo split with combined chunks.
// ---------------------------------------------------------------------------

#define SEQ    1024
#define DIN    2048
#define FUSEDC 4096
#define HV     16
#define DOVG   2048
#define GK     2048

// ------------------------- scratch (static, no alloc) ----------------------
__device__ float g_qkv_pre[SEQ * FUSEDC];
__device__ float g_qkv[SEQ * FUSEDC];
__device__ float g_gate[SEQ * DOVG];
__device__ float g_ctx[SEQ * DOVG];
__device__ float g_beta[HV * SEQ];
__device__ float g_alpha[HV * SEQ];

__device__ __nv_bfloat16 g_x_hi[SEQ * DIN],       g_x_lo[SEQ * DIN];
__device__ __nv_bfloat16 g_wqkv_hi[FUSEDC * DIN], g_wqkv_lo[FUSEDC * DIN];
__device__ __nv_bfloat16 g_wg_hi[DOVG * DIN],     g_wg_lo[DOVG * DIN];
__device__ __nv_bfloat16 g_wo_hi[DOVG * DIN],     g_wo_lo[DOVG * DIN];
__device__ __nv_bfloat16 g_gctx_hi[SEQ * DOVG],   g_gctx_lo[SEQ * DOVG];
// beta(16)+alpha(16) weight rows, zero-padded to 128 rows (zero-init at load,
// rows 32..127 never written -> stay zero).
__device__ __nv_bfloat16 g_wba_hi[128 * DIN],     g_wba_lo[128 * DIN];

// ------------------------- helpers -----------------------------------------
__device__ __forceinline__ uint32_t smem_u32(const void* p) {
    uint32_t a;
    asm("{ .reg .u64 t; cvta.to.shared.u64 t, %1; cvt.u32.u64 %0, t; }"
        : "=r"(a) : "l"(p));
    return a;
}
__device__ __forceinline__ void cp_async16(uint32_t dst, const void* src) {
    asm volatile("cp.async.cg.shared.global [%0], [%1], 16;"
                 :: "r"(dst), "l"(src));
}
__device__ __forceinline__ void cp_async4(uint32_t dst, const void* src) {
    asm volatile("cp.async.ca.shared.global [%0], [%1], 4;"
                 :: "r"(dst), "l"(src));
}
__device__ __forceinline__ void cp_commit() {
    asm volatile("cp.async.commit_group;");
}
__device__ __forceinline__ void ldmatrix_x4(uint32_t* r, uint32_t addr) {
    asm volatile("ldmatrix.sync.aligned.m8n8.x4.shared.b16 {%0,%1,%2,%3}, [%4];"
                 : "=r"(r[0]), "=r"(r[1]), "=r"(r[2]), "=r"(r[3]) : "r"(addr));
}
__device__ __forceinline__ void ldmatrix_x2(uint32_t* r, uint32_t addr) {
    asm volatile("ldmatrix.sync.aligned.m8n8.x2.shared.b16 {%0,%1}, [%2];"
                 : "=r"(r[0]), "=r"(r[1]) : "r"(addr));
}
__device__ __forceinline__ void mma16816(float* d, const uint32_t* a, const uint32_t* b) {
    asm volatile("mma.sync.aligned.m16n8k16.row.col.f32.bf16.bf16.f32 "
                 "{%0,%1,%2,%3}, {%4,%5,%6,%7}, {%8,%9}, {%0,%1,%2,%3};"
                 : "+f"(d[0]), "+f"(d[1]), "+f"(d[2]), "+f"(d[3])
                 : "r"(a[0]), "r"(a[1]), "r"(a[2]), "r"(a[3]),
                   "r"(b[0]), "r"(b[1]));
}
__device__ __forceinline__ float silu(float v) { return v / (1.f + expf(-v)); }

// ---------------------------------------------------------------------------
// Combined-chunk 3-pass split-bf16 GEMM.
//   C[1024, N] = A[1024, 2048] * B[N, 2048]^T
// Per K=32 chunk stage holds Ahi|Alo|Bhi|Blo; MMAs: hi*hi + hi*lo + lo*hi.
// CTA 128x128, 8 warps (2m x 4n), warp tile 64x32, 2 stages, 2 CTA/SM.
// Column segments: [0,N1): B1/C1 epi1, [N1,N1+N2): B2/C2 epi2,
// [N1+N2, +N3): beta/alpha special epilogue.
// epi codes: 0 = store, 1 = silu+store.
// ---------------------------------------------------------------------------
#define SASTR   40
#define ARR_B   10240                 // bytes per operand array per stage
#define STAGEB  (4 * ARR_B)           // 40960
#define GSMEM   (2 * STAGEB)          // 81920
#define NCHT    (GK / 32)             // 64 chunks total

__global__ void __launch_bounds__(256, 2) gemm3c(
    const __nv_bfloat16* __restrict__ Ahi, const __nv_bfloat16* __restrict__ Alo,
    const __nv_bfloat16* __restrict__ B1h, const __nv_bfloat16* __restrict__ B1l,
    float* __restrict__ C1, int N1, int epi1,
    const __nv_bfloat16* __restrict__ B2h, const __nv_bfloat16* __restrict__ B2l,
    float* __restrict__ C2, int N2, int epi2,
    const __nv_bfloat16* __restrict__ B3h, const __nv_bfloat16* __restrict__ B3l,
    int N3,
    const float* __restrict__ log_A, const float* __restrict__ dt_bias,
    float* __restrict__ beta_out, float* __restrict__ alpha_out)
{
    extern __shared__ char dynsmem[];
    const uint32_t sb = smem_u32(dynsmem);

    const int tid  = threadIdx.x;
    const int lane = tid & 31;
    const int wrp  = tid >> 5;
    const int wm   = wrp >> 2;
    const int wn   = wrp & 3;
    const int bm   = blockIdx.y * 128;

    int gx = blockIdx.x * 128;
    const __nv_bfloat16 *BH, *BL;
    float* Cp = 0;
    int N = 0, epi, bn;
    if (gx < N1)            { BH = B1h; BL = B1l; Cp = C1; N = N1; epi = epi1; bn = gx; }
    else if (gx < N1 + N2)  { BH = B2h; BL = B2l; Cp = C2; N = N2; epi = epi2; bn = gx - N1; }
    else                    { BH = B3h; BL = B3l; epi = 3; bn = gx - N1 - N2; (void)N3; }

    const int ld_row = tid >> 2;
    const int ld_seg = (tid & 3) * 8;
    const uint32_t st_off = (uint32_t)(ld_row * SASTR + ld_seg) * 2;

    const int a_row = wm * 64 + (lane & 15);
    const int a_ko  = (lane >> 4) * 8;
    const uint32_t aH0 = sb + (uint32_t)(a_row * SASTR + a_ko) * 2;
    const int b_row = wn * 32 + (lane & 7);
    const int b_ko  = ((lane >> 3) & 1) * 8;
    const uint32_t bH0 = sb + 2 * ARR_B + (uint32_t)(b_row * SASTR + b_ko) * 2;

    float acc[4][4][4];
#pragma unroll
    for (int i = 0; i < 4; ++i)
#pragma unroll
        for (int j = 0; j < 4; ++j)
#pragma unroll
            for (int q = 0; q < 4; ++q) acc[i][j][q] = 0.f;

    // issue one combined chunk (Ahi,Alo,Bhi,Blo) into a stage
#define ISSUE_CHUNK(stagebase, kc)                                             \
    do {                                                                       \
        _Pragma("unroll")                                                      \
        for (int it = 0; it < 2; ++it) {                                       \
            int row = ld_row + it * 64;                                        \
            uint32_t o = st_off + (uint32_t)(it * 64 * SASTR) * 2;             \
            size_t ga = (size_t)(bm + row) * GK + (kc) + ld_seg;               \
            size_t gb = (size_t)(bn + row) * GK + (kc) + ld_seg;               \
            cp_async16((stagebase) + o,              Ahi + ga);                \
            cp_async16((stagebase) + ARR_B + o,      Alo + ga);                \
            cp_async16((stagebase) + 2 * ARR_B + o,  BH + gb);                 \
            cp_async16((stagebase) + 3 * ARR_B + o,  BL + gb);                 \
        }                                                                      \
    } while (0)

    ISSUE_CHUNK(sb, 0);
    cp_commit();
    ISSUE_CHUNK(sb + STAGEB, 32);
    cp_commit();

    for (int c = 0; c < NCHT; ++c) {
        asm volatile("cp.async.wait_group 1;");
        __syncthreads();

        const uint32_t soff = (uint32_t)(c & 1) * STAGEB;
#pragma unroll
        for (int ks = 0; ks < 2; ++ks) {
            uint32_t ah[4][4], bh[4][2], bl[4][2];
#pragma unroll
            for (int mt = 0; mt < 4; ++mt)
                ldmatrix_x4(ah[mt], aH0 + soff + mt * (16 * SASTR * 2) + ks * 32);
#pragma unroll
            for (int nt = 0; nt < 4; ++nt)
                ldmatrix_x2(bh[nt], bH0 + soff + nt * (8 * SASTR * 2) + ks * 32);
#pragma unroll
            for (int mt = 0; mt < 4; ++mt)
#pragma unroll
                for (int nt = 0; nt < 4; ++nt)
                    mma16816(acc[mt][nt], ah[mt], bh[nt]);
#pragma unroll
            for (int nt = 0; nt < 4; ++nt)
                ldmatrix_x2(bl[nt], bH0 + ARR_B + soff + nt * (8 * SASTR * 2) + ks * 32);
#pragma unroll
            for (int mt = 0; mt < 4; ++mt)
#pragma unroll
                for (int nt = 0; nt < 4; ++nt)
                    mma16816(acc[mt][nt], ah[mt], bl[nt]);
#pragma unroll
            for (int mt = 0; mt < 4; ++mt)
                ldmatrix_x4(ah[mt], aH0 + ARR_B + soff + mt * (16 * SASTR * 2) + ks * 32);
#pragma unroll
            for (int mt = 0; mt < 4; ++mt)
#pragma unroll
                for (int nt = 0; nt < 4; ++nt)
                    mma16816(acc[mt][nt], ah[mt], bh[nt]);
        }
        __syncthreads();

        if (c + 2 < NCHT) {
            const uint32_t so = sb + (uint32_t)(c & 1) * STAGEB;
            ISSUE_CHUNK(so, (c + 2) * 32);
        }
        cp_commit();
    }
#undef ISSUE_CHUNK

    // ---- epilogue ----
    if (epi == 3) {
        // beta/alpha: cols 0..31 live (warp wn==0), value at (row=t, col=idx)
        if (wn != 0 || bn != 0) return;
#pragma unroll
        for (int mt = 0; mt < 4; ++mt) {
            int row0 = bm + wm * 64 + mt * 16 + (lane >> 2);
#pragma unroll
            for (int nt = 0; nt < 4; ++nt) {
#pragma unroll
                for (int half = 0; half < 2; ++half) {
#pragma unroll
                    for (int e = 0; e < 2; ++e) {
                        int col = nt * 8 + (lane & 3) * 2 + e;
                        int t = row0 + half * 8;
                        float v = acc[mt][nt][half * 2 + e];
                        if (col < 16) {
                            beta_out[col * SEQ + t] = 1.f / (1.f + expf(-v));
                        } else {
                            int h = col - 16;
                            float z = v + dt_bias[h];
                            float sp = (z > 20.f) ? z : log1pf(expf(z));
                            alpha_out[h * SEQ + t] = expf(-expf(log_A[h]) * sp);
                        }
                    }
                }
            }
        }
        return;
    }
#pragma unroll
    for (int mt = 0; mt < 4; ++mt) {
        int row0 = bm + wm * 64 + mt * 16 + (lane >> 2);
#pragma unroll
        for (int nt = 0; nt < 4; ++nt) {
            int col = bn + wn * 32 + nt * 8 + (lane & 3) * 2;
            float2 v0 = make_float2(acc[mt][nt][0], acc[mt][nt][1]);
            float2 v1 = make_float2(acc[mt][nt][2], acc[mt][nt][3]);
            if (epi == 1) {
                v0.x = silu(v0.x); v0.y = silu(v0.y);
                v1.x = silu(v1.x); v1.y = silu(v1.y);
            }
            *(float2*)(Cp + (size_t)row0 * N + col) = v0;
            *(float2*)(Cp + (size_t)(row0 + 8) * N + col) = v1;
        }
    }
}

// ---------------------------------------------------------------------------
// one-shot fp32 -> (bf16 hi, lo) split over all operands
// segments: x | w_qkv | w_gate | w_out | w_beta | w_alpha
// ---------------------------------------------------------------------------
#define N4_X   (SEQ * DIN / 4)
#define N4_QKV (FUSEDC * DIN / 4)
#define N4_WG  (DOVG * DIN / 4)
#define N4_WO  (DOVG * DIN / 4)
#define N4_WB  (16 * DIN / 4)
#define N4_WA  (16 * DIN / 4)
#define N4_TOT (N4_X + N4_QKV + N4_WG + N4_WO + N4_WB + N4_WA)

__global__ void __launch_bounds__(256) split_all(
    const float* __restrict__ x, const float* __restrict__ wqkv,
    const float* __restrict__ wg, const float* __restrict__ wo,
    const float* __restrict__ wb, const float* __restrict__ wa,
    __nv_bfloat16* xh, __nv_bfloat16* xl,
    __nv_bfloat16* qh, __nv_bfloat16* ql,
    __nv_bfloat16* gh, __nv_bfloat16* gl,
    __nv_bfloat16* oh, __nv_bfloat16* ol,
    __nv_bfloat16* bah, __nv_bfloat16* bal)
{
    int i = blockIdx.x * 256 + threadIdx.x;
    if (i >= N4_TOT) return;
    const float* src;
    __nv_bfloat16 *hi, *lo;
    if (i < N4_X) { src = x; hi = xh; lo = xl; }
    else if ((i -= N4_X) < N4_QKV) { src = wqkv; hi = qh; lo = ql; }
    else if ((i -= N4_QKV) < N4_WG) { src = wg; hi = gh; lo = gl; }
    else if ((i -= N4_WG) < N4_WO) { src = wo; hi = oh; lo = ol; }
    else if ((i -= N4_WO) < N4_WB) { src = wb; hi = bah; lo = bal; }
    else { i -= N4_WB; src = wa; hi = bah + 16 * DIN; lo = bal + 16 * DIN; }

    float4 v = ((const float4*)src)[i];
    __nv_bfloat16 h0 = __float2bfloat16(v.x), h1 = __float2bfloat16(v.y);
    __nv_bfloat16 h2 = __float2bfloat16(v.z), h3 = __float2bfloat16(v.w);
    __nv_bfloat16 l0 = __float2bfloat16(v.x - __bfloat162float(h0));
    __nv_bfloat16 l1 = __float2bfloat16(v.y - __bfloat162float(h1));
    __nv_bfloat16 l2 = __float2bfloat16(v.z - __bfloat162float(h2));
    __nv_bfloat16 l3 = __float2bfloat16(v.w - __bfloat162float(h3));
    ((__nv_bfloat162*)hi)[i * 2 + 0] = __halves2bfloat162(h0, h1);
    ((__nv_bfloat162*)hi)[i * 2 + 1] = __halves2bfloat162(h2, h3);
    ((__nv_bfloat162*)lo)[i * 2 + 0] = __halves2bfloat162(l0, l1);
    ((__nv_bfloat162*)lo)[i * 2 + 1] = __halves2bfloat162(l2, l3);
}

// ---------------------------------------------------------------------------
// causal depthwise conv1d (K=4) + SiLU + fused l2norm for q/k head blocks
// grid (SEQ/4, 32), 128 threads; thread owns one channel, 4 timesteps rolling
// ---------------------------------------------------------------------------
__global__ void __launch_bounds__(128) conv_l2_kernel(
    const float* __restrict__ in, const float* __restrict__ w,
    float* __restrict__ out)
{
    const int t0  = blockIdx.x * 4;
    const int blk = blockIdx.y;
    const int tid = threadIdx.x;
    const int c   = blk * 128 + tid;
    const int lane = tid & 31;
    const int wrp  = tid >> 5;

    float4 wc = *(const float4*)(w + c * 4);
    const float* col = in + c;

    float p1 = (t0 >= 1) ? col[(size_t)(t0 - 1) * FUSEDC] : 0.f;
    float p2 = (t0 >= 2) ? col[(size_t)(t0 - 2) * FUSEDC] : 0.f;
    float p3 = (t0 >= 3) ? col[(size_t)(t0 - 3) * FUSEDC] : 0.f;
    float c0 = col[(size_t)(t0 + 0) * FUSEDC];
    float c1 = col[(size_t)(t0 + 1) * FUSEDC];
    float c2 = col[(size_t)(t0 + 2) * FUSEDC];
    float c3 = col[(size_t)(t0 + 3) * FUSEDC];

    float v[4];
    v[0] = silu(wc.w * c0 + wc.z * p1 + wc.y * p2 + wc.x * p3);
    v[1] = silu(wc.w * c1 + wc.z * c0 + wc.y * p1 + wc.x * p2);
    v[2] = silu(wc.w * c2 + wc.z * c1 + wc.y * c0 + wc.x * p1);
    v[3] = silu(wc.w * c3 + wc.z * c2 + wc.y * c1 + wc.x * c0);

    if (blk < 16) {
        __shared__ float sred[4][128];
        __shared__ float sscale[4];
#pragma unroll
        for (int i = 0; i < 4; ++i) sred[i][tid] = v[i] * v[i];
        __syncthreads();
        // warp w reduces timestep w
        float s = sred[wrp][lane] + sred[wrp][lane + 32] +
                  sred[wrp][lane + 64] + sred[wrp][lane + 96];
#pragma unroll
        for (int m = 16; m; m >>= 1) s += __shfl_xor_sync(0xffffffffu, s, m);
        if (lane == 0) {
            float sc = rsqrtf(s + 1e-6f);
            if (blk < 8) sc *= 0.08838834764831845f;   // q: fold DK^-0.5
            sscale[wrp] = sc;
        }
        __syncthreads();
#pragma unroll
        for (int i = 0; i < 4; ++i) v[i] *= sscale[i];
    }
#pragma unroll
    for (int i = 0; i < 4; ++i)
        out[(size_t)(t0 + i) * FUSEDC + c] = v[i];
}

// ---------------------------------------------------------------------------
// Gated delta-rule scan, cp.async double-buffered chunks.
// grid 128 = 16 heads x 8 column blocks; 256 threads.
// dyn smem per buf (floats): sq 4096 | sk 4096 | sv 512 | sb 32 | sa 32 = 8768
// ---------------------------------------------------------------------------
#define TSCHUNK 32
#define SCAN_BUF_F 8768
#define SCAN_SMEM (2 * SCAN_BUF_F * 4)

__global__ void __launch_bounds__(256) scan_kernel(
    const float* __restrict__ qkv, const float* __restrict__ beta,
    const float* __restrict__ alpha, float* __restrict__ ctx)
{
    extern __shared__ float ss[];
    const int h  = blockIdx.x >> 3;
    const int cb = blockIdx.x & 7;
    const int hq = h >> 1;
    const int tid  = threadIdx.x;
    const int lane = tid & 31;
    const int warp = tid >> 5;
    const int j    = (warp << 1) | (lane >> 4);
    const int sub  = lane & 15;

    const uint32_t ssb = smem_u32(ss);

    const float* qbase = qkv + hq * 128;
    const float* kbase = qkv + 1024 + hq * 128;
    const float* vbase = qkv + 2048 + h * 128 + cb * 16;
    const float* bbase = beta + h * SEQ;
    const float* abase = alpha + h * SEQ;
    float* obase = ctx + h * 128 + cb * 16 + j;

#define SCAN_ISSUE(buf, t0)                                                    \
    do {                                                                       \
        uint32_t sbb = ssb + (uint32_t)(buf) * (SCAN_BUF_F * 4);               \
        _Pragma("unroll")                                                      \
        for (int u = 0; u < 4; ++u) {                                          \
            int lin = tid + u * 256;                                           \
            int tt = lin >> 5, d4 = lin & 31;                                  \
            size_t goff = (size_t)((t0) + tt) * FUSEDC + d4 * 4;               \
            cp_async16(sbb + (uint32_t)lin * 16, qbase + goff);                \
            cp_async16(sbb + 16384 + (uint32_t)lin * 16, kbase + goff);        \
        }                                                                      \
        if (tid < 128) {                                                       \
            int tt = tid >> 2, j4 = tid & 3;                                   \
            cp_async16(sbb + 32768 + (uint32_t)tid * 16,                       \
                       vbase + (size_t)((t0) + tt) * FUSEDC + j4 * 4);         \
        } else if (tid < 160) {                                                \
            cp_async4(sbb + 34816 + (uint32_t)(tid - 128) * 4,                 \
                      bbase + (t0) + tid - 128);                               \
        } else if (tid < 192) {                                                \
            cp_async4(sbb + 34944 + (uint32_t)(tid - 160) * 4,                 \
                      abase + (t0) + tid - 160);                               \
        }                                                                      \
        cp_commit();                                                           \
    } while (0)

    float S[8];
#pragma unroll
    for (int i = 0; i < 8; ++i) S[i] = 0.f;

    SCAN_ISSUE(0, 0);

    for (int ci = 0; ci < SEQ / TSCHUNK; ++ci) {
        asm volatile("cp.async.wait_group 0;");
        __syncthreads();
        if (ci + 1 < SEQ / TSCHUNK) SCAN_ISSUE((ci + 1) & 1, (ci + 1) * TSCHUNK);

        const float* sqf = ss + (ci & 1) * SCAN_BUF_F;
        const float* skf = sqf + 4096;
        const float* svf = sqf + 8192;
        const float* sbf = sqf + 8704;
        const float* saf = sqf + 8736;
        const int t0 = ci * TSCHUNK;

        for (int tt = 0; tt < TSCHUNK; ++tt) {
            float a = saf[tt], b = sbf[tt];
            float kr[8], qr[8];
            *(float4*)(kr)     = *(const float4*)&skf[tt * 128 + sub * 8];
            *(float4*)(kr + 4) = *(const float4*)&skf[tt * 128 + sub * 8 + 4];
            *(float4*)(qr)     = *(const float4*)&sqf[tt * 128 + sub * 8];
            *(float4*)(qr + 4) = *(const float4*)&sqf[tt * 128 + sub * 8 + 4];

            float kv0 = 0.f, kv1 = 0.f;
#pragma unroll
            for (int i = 0; i < 8; i += 2) {
                kv0 = fmaf(kr[i],     S[i],     kv0);
                kv1 = fmaf(kr[i + 1], S[i + 1], kv1);
            }
            float kv = kv0 + kv1;
            kv += __shfl_xor_sync(0xffffffffu, kv, 1);
            kv += __shfl_xor_sync(0xffffffffu, kv, 2);
            kv += __shfl_xor_sync(0xffffffffu, kv, 4);
            kv += __shfl_xor_sync(0xffffffffu, kv, 8);
            float uval = (svf[tt * 16 + j] - a * kv) * b;
            float o0 = 0.f, o1 = 0.f;
#pragma unroll
            for (int i = 0; i < 8; ++i)
                S[i] = fmaf(a, S[i], kr[i] * uval);
#pragma unroll
            for (int i = 0; i < 8; i += 2) {
                o0 = fmaf(qr[i],     S[i],     o0);
                o1 = fmaf(qr[i + 1], S[i + 1], o1);
            }
            float o = o0 + o1;
            o += __shfl_xor_sync(0xffffffffu, o, 1);
            o += __shfl_xor_sync(0xffffffffu, o, 2);
            o += __shfl_xor_sync(0xffffffffu, o, 4);
            o += __shfl_xor_sync(0xffffffffu, o, 8);
            if (sub == 0) obase[(size_t)(t0 + tt) * DOVG] = o;
        }
        __syncthreads();
    }
#undef SCAN_ISSUE
}

// ---------------------------------------------------------------------------
// rms_norm(ctx) * rms_w * gate -> split bf16 (hi/lo)
// ---------------------------------------------------------------------------
__global__ void __launch_bounds__(128) rms_gate_kernel(
    const float* __restrict__ ctx, const float* __restrict__ gate,
    const float* __restrict__ rms_w,
    __nv_bfloat16* __restrict__ ghi, __nv_bfloat16* __restrict__ glo)
{
    const int t = blockIdx.x;
    const int h = blockIdx.y;
    const int tid = threadIdx.x;
    size_t idx = (size_t)t * DOVG + h * 128 + tid;
    float v = ctx[idx];
    float ss = v * v;
#pragma unroll
    for (int m = 16; m; m >>= 1) ss += __shfl_xor_sync(0xffffffffu, ss, m);
    __shared__ float sw[4];
    if ((tid & 31) == 0) sw[tid >> 5] = ss;
    __syncthreads();
    float tot = sw[0] + sw[1] + sw[2] + sw[3];
    float sc = rsqrtf(tot * (1.f / 128.f) + 1e-6f);
    float r = v * sc * rms_w[tid] * gate[idx];
    __nv_bfloat16 hh = __float2bfloat16(r);
    ghi[idx] = hh;
    glo[idx] = __float2bfloat16(r - __bfloat162float(hh));
}

// ---------------------------------------------------------------------------
extern "C" void kernel_launch(void* const* d_in, const int* in_sizes, int n_in,
                              void* d_out, int out_size)
{
    const float* x       = (const float*)d_in[0];
    const float* w_qkv   = (const float*)d_in[1];
    const float* w_gate  = (const float*)d_in[2];
    const float* w_beta  = (const float*)d_in[3];
    const float* w_alpha = (const float*)d_in[4];
    const float* log_A   = (const float*)d_in[5];
    const float* dt_bias = (const float*)d_in[6];
    const float* conv_w  = (const float*)d_in[7];
    const float* rms_w   = (const float*)d_in[8];
    const float* w_out   = (const float*)d_in[9];
    float* out = (float*)d_out;

    float *qkv_pre, *qkv, *gate, *ctx, *beta, *alpha;
    __nv_bfloat16 *x_hi, *x_lo, *wqkv_hi, *wqkv_lo, *wg_hi, *wg_lo,
                  *wo_hi, *wo_lo, *gctx_hi, *gctx_lo, *wba_hi, *wba_lo;
    cudaGetSymbolAddress((void**)&qkv_pre, g_qkv_pre);
    cudaGetSymbolAddress((void**)&qkv,     g_qkv);
    cudaGetSymbolAddress((void**)&gate,    g_gate);
    cudaGetSymbolAddress((void**)&ctx,     g_ctx);
    cudaGetSymbolAddress((void**)&beta,    g_beta);
    cudaGetSymbolAddress((void**)&alpha,   g_alpha);
    cudaGetSymbolAddress((void**)&x_hi,    g_x_hi);
    cudaGetSymbolAddress((void**)&x_lo,    g_x_lo);
    cudaGetSymbolAddress((void**)&wqkv_hi, g_wqkv_hi);
    cudaGetSymbolAddress((void**)&wqkv_lo, g_wqkv_lo);
    cudaGetSymbolAddress((void**)&wg_hi,   g_wg_hi);
    cudaGetSymbolAddress((void**)&wg_lo,   g_wg_lo);
    cudaGetSymbolAddress((void**)&wo_hi,   g_wo_hi);
    cudaGetSymbolAddress((void**)&wo_lo,   g_wo_lo);
    cudaGetSymbolAddress((void**)&gctx_hi, g_gctx_hi);
    cudaGetSymbolAddress((void**)&gctx_lo, g_gctx_lo);
    cudaGetSymbolAddress((void**)&wba_hi,  g_wba_hi);
    cudaGetSymbolAddress((void**)&wba_lo,  g_wba_lo);

    cudaFuncSetAttribute(gemm3c, cudaFuncAttributeMaxDynamicSharedMemorySize, GSMEM);
    cudaFuncSetAttribute(scan_kernel, cudaFuncAttributeMaxDynamicSharedMemorySize, SCAN_SMEM);

    // 0) one-shot precision splits
    split_all<<<(N4_TOT + 255) / 256, 256>>>(
        x, w_qkv, w_gate, w_out, w_beta, w_alpha,
        x_hi, x_lo, wqkv_hi, wqkv_lo, wg_hi, wg_lo, wo_hi, wo_lo, wba_hi, wba_lo);

    // 1) fused qkv + gate + beta/alpha projections
    gemm3c<<<dim3((FUSEDC + DOVG + 128) / 128, SEQ / 128), 256, GSMEM>>>(
        x_hi, x_lo,
        wqkv_hi, wqkv_lo, qkv_pre, FUSEDC, 0,
        wg_hi, wg_lo, gate, DOVG, 1,
        wba_hi, wba_lo, 128,
        log_A, dt_bias, beta, alpha);

    // 2) causal depthwise conv + silu + fused l2norm on q/k
    conv_l2_kernel<<<dim3(SEQ / 4, 32), 128>>>(qkv_pre, conv_w, qkv);

    // 3) gated delta-rule scan
    scan_kernel<<<128, 256, SCAN_SMEM>>>(qkv, beta, alpha, ctx);

    // 4) rms norm * gate -> split bf16
    rms_gate_kernel<<<dim3(SEQ, HV), 128>>>(ctx, gate, rms_w, gctx_hi, gctx_lo);

    // 5) output projection
    gemm3c<<<dim3(DOVG / 128, SEQ / 128), 256, GSMEM>>>(
        gctx_hi, gctx_lo,
        wo_hi, wo_lo, out, DOVG, 0,
        (const __nv_bfloat16*)0, (const __nv_bfloat16*)0, (float*)0, 0, 0,
        (const __nv_bfloat16*)0, (const __nv_bfloat16*)0, 0,
        log_A, dt_bias, beta, alpha);
}

// round 6
// speedup vs baseline: 4.0943x; 1.2280x over previous
#include <cuda_runtime.h>
#include <cuda_bf16.h>
#include <math.h>
#include <stdint.h>

// ---------------------------------------------------------------------------
// FusedGatedDeltaNet: B=1, S=1024, D_IN=2048, H_QK=8, H_V=16, DK=DV=128,
// KCONV=4, FUSED=4096, D_OUT=1024, D_OUT_VG=2048
// GEMMs: mma.sync bf16 m16n8k16, 3-pass hi/lo split with combined chunks.
// Scan: 256 CTAs x 128 thr, swizzled smem (bank-conflict-free), short chain.
// ---------------------------------------------------------------------------

#define SEQ    1024
#define DIN    2048
#define FUSEDC 4096
#define HV     16
#define DOVG   2048
#define GK     2048

// ------------------------- scratch (static, no alloc) ----------------------
__device__ float g_qkv_pre[SEQ * FUSEDC];
__device__ float g_qkv[SEQ * FUSEDC];
__device__ float g_gate[SEQ * DOVG];
__device__ float g_ctx[SEQ * DOVG];
__device__ float g_beta[HV * SEQ];
__device__ float g_alpha[HV * SEQ];

__device__ __nv_bfloat16 g_x_hi[SEQ * DIN],       g_x_lo[SEQ * DIN];
__device__ __nv_bfloat16 g_wqkv_hi[FUSEDC * DIN], g_wqkv_lo[FUSEDC * DIN];
__device__ __nv_bfloat16 g_wg_hi[DOVG * DIN],     g_wg_lo[DOVG * DIN];
__device__ __nv_bfloat16 g_wo_hi[DOVG * DIN],     g_wo_lo[DOVG * DIN];
__device__ __nv_bfloat16 g_gctx_hi[SEQ * DOVG],   g_gctx_lo[SEQ * DOVG];
// beta(16)+alpha(16) weight rows zero-padded to 128 rows
__device__ __nv_bfloat16 g_wba_hi[128 * DIN],     g_wba_lo[128 * DIN];

// ------------------------- helpers -----------------------------------------
__device__ __forceinline__ uint32_t smem_u32(const void* p) {
    uint32_t a;
    asm("{ .reg .u64 t; cvta.to.shared.u64 t, %1; cvt.u32.u64 %0, t; }"
        : "=r"(a) : "l"(p));
    return a;
}
__device__ __forceinline__ void cp_async16(uint32_t dst, const void* src) {
    asm volatile("cp.async.cg.shared.global [%0], [%1], 16;"
                 :: "r"(dst), "l"(src));
}
__device__ __forceinline__ void cp_async4(uint32_t dst, const void* src) {
    asm volatile("cp.async.ca.shared.global [%0], [%1], 4;"
                 :: "r"(dst), "l"(src));
}
__device__ __forceinline__ void cp_commit() {
    asm volatile("cp.async.commit_group;");
}
__device__ __forceinline__ void ldmatrix_x4(uint32_t* r, uint32_t addr) {
    asm volatile("ldmatrix.sync.aligned.m8n8.x4.shared.b16 {%0,%1,%2,%3}, [%4];"
                 : "=r"(r[0]), "=r"(r[1]), "=r"(r[2]), "=r"(r[3]) : "r"(addr));
}
__device__ __forceinline__ void ldmatrix_x2(uint32_t* r, uint32_t addr) {
    asm volatile("ldmatrix.sync.aligned.m8n8.x2.shared.b16 {%0,%1}, [%2];"
                 : "=r"(r[0]), "=r"(r[1]) : "r"(addr));
}
__device__ __forceinline__ void mma16816(float* d, const uint32_t* a, const uint32_t* b) {
    asm volatile("mma.sync.aligned.m16n8k16.row.col.f32.bf16.bf16.f32 "
                 "{%0,%1,%2,%3}, {%4,%5,%6,%7}, {%8,%9}, {%0,%1,%2,%3};"
                 : "+f"(d[0]), "+f"(d[1]), "+f"(d[2]), "+f"(d[3])
                 : "r"(a[0]), "r"(a[1]), "r"(a[2]), "r"(a[3]),
                   "r"(b[0]), "r"(b[1]));
}
__device__ __forceinline__ float silu(float v) { return v / (1.f + expf(-v)); }

// ---------------------------------------------------------------------------
// Combined-chunk 3-pass split-bf16 GEMM (unchanged from R5 — passing)
// ---------------------------------------------------------------------------
#define SASTR   40
#define ARR_B   10240
#define STAGEB  (4 * ARR_B)
#define GSMEM   (2 * STAGEB)
#define NCHT    (GK / 32)

__global__ void __launch_bounds__(256, 2) gemm3c(
    const __nv_bfloat16* __restrict__ Ahi, const __nv_bfloat16* __restrict__ Alo,
    const __nv_bfloat16* __restrict__ B1h, const __nv_bfloat16* __restrict__ B1l,
    float* __restrict__ C1, int N1, int epi1,
    const __nv_bfloat16* __restrict__ B2h, const __nv_bfloat16* __restrict__ B2l,
    float* __restrict__ C2, int N2, int epi2,
    const __nv_bfloat16* __restrict__ B3h, const __nv_bfloat16* __restrict__ B3l,
    int N3,
    const float* __restrict__ log_A, const float* __restrict__ dt_bias,
    float* __restrict__ beta_out, float* __restrict__ alpha_out)
{
    extern __shared__ char dynsmem[];
    const uint32_t sb = smem_u32(dynsmem);

    const int tid  = threadIdx.x;
    const int lane = tid & 31;
    const int wrp  = tid >> 5;
    const int wm   = wrp >> 2;
    const int wn   = wrp & 3;
    const int bm   = blockIdx.y * 128;

    int gx = blockIdx.x * 128;
    const __nv_bfloat16 *BH, *BL;
    float* Cp = 0;
    int N = 0, epi, bn;
    if (gx < N1)            { BH = B1h; BL = B1l; Cp = C1; N = N1; epi = epi1; bn = gx; }
    else if (gx < N1 + N2)  { BH = B2h; BL = B2l; Cp = C2; N = N2; epi = epi2; bn = gx - N1; }
    else                    { BH = B3h; BL = B3l; epi = 3; bn = gx - N1 - N2; (void)N3; }

    const int ld_row = tid >> 2;
    const int ld_seg = (tid & 3) * 8;
    const uint32_t st_off = (uint32_t)(ld_row * SASTR + ld_seg) * 2;

    const int a_row = wm * 64 + (lane & 15);
    const int a_ko  = (lane >> 4) * 8;
    const uint32_t aH0 = sb + (uint32_t)(a_row * SASTR + a_ko) * 2;
    const int b_row = wn * 32 + (lane & 7);
    const int b_ko  = ((lane >> 3) & 1) * 8;
    const uint32_t bH0 = sb + 2 * ARR_B + (uint32_t)(b_row * SASTR + b_ko) * 2;

    float acc[4][4][4];
#pragma unroll
    for (int i = 0; i < 4; ++i)
#pragma unroll
        for (int j = 0; j < 4; ++j)
#pragma unroll
            for (int q = 0; q < 4; ++q) acc[i][j][q] = 0.f;

#define ISSUE_CHUNK(stagebase, kc)                                             \
    do {                                                                       \
        _Pragma("unroll")                                                      \
        for (int it = 0; it < 2; ++it) {                                       \
            int row = ld_row + it * 64;                                        \
            uint32_t o = st_off + (uint32_t)(it * 64 * SASTR) * 2;             \
            size_t ga = (size_t)(bm + row) * GK + (kc) + ld_seg;               \
            size_t gb = (size_t)(bn + row) * GK + (kc) + ld_seg;               \
            cp_async16((stagebase) + o,              Ahi + ga);                \
            cp_async16((stagebase) + ARR_B + o,      Alo + ga);                \
            cp_async16((stagebase) + 2 * ARR_B + o,  BH + gb);                 \
            cp_async16((stagebase) + 3 * ARR_B + o,  BL + gb);                 \
        }                                                                      \
    } while (0)

    ISSUE_CHUNK(sb, 0);
    cp_commit();
    ISSUE_CHUNK(sb + STAGEB, 32);
    cp_commit();

    for (int c = 0; c < NCHT; ++c) {
        asm volatile("cp.async.wait_group 1;");
        __syncthreads();

        const uint32_t soff = (uint32_t)(c & 1) * STAGEB;
#pragma unroll
        for (int ks = 0; ks < 2; ++ks) {
            uint32_t ah[4][4], bh[4][2], bl[4][2];
#pragma unroll
            for (int mt = 0; mt < 4; ++mt)
                ldmatrix_x4(ah[mt], aH0 + soff + mt * (16 * SASTR * 2) + ks * 32);
#pragma unroll
            for (int nt = 0; nt < 4; ++nt)
                ldmatrix_x2(bh[nt], bH0 + soff + nt * (8 * SASTR * 2) + ks * 32);
#pragma unroll
            for (int mt = 0; mt < 4; ++mt)
#pragma unroll
                for (int nt = 0; nt < 4; ++nt)
                    mma16816(acc[mt][nt], ah[mt], bh[nt]);
#pragma unroll
            for (int nt = 0; nt < 4; ++nt)
                ldmatrix_x2(bl[nt], bH0 + ARR_B + soff + nt * (8 * SASTR * 2) + ks * 32);
#pragma unroll
            for (int mt = 0; mt < 4; ++mt)
#pragma unroll
                for (int nt = 0; nt < 4; ++nt)
                    mma16816(acc[mt][nt], ah[mt], bl[nt]);
#pragma unroll
            for (int mt = 0; mt < 4; ++mt)
                ldmatrix_x4(ah[mt], aH0 + ARR_B + soff + mt * (16 * SASTR * 2) + ks * 32);
#pragma unroll
            for (int mt = 0; mt < 4; ++mt)
#pragma unroll
                for (int nt = 0; nt < 4; ++nt)
                    mma16816(acc[mt][nt], ah[mt], bh[nt]);
        }
        __syncthreads();

        if (c + 2 < NCHT) {
            const uint32_t so = sb + (uint32_t)(c & 1) * STAGEB;
            ISSUE_CHUNK(so, (c + 2) * 32);
        }
        cp_commit();
    }
#undef ISSUE_CHUNK

    if (epi == 3) {
        if (wn != 0 || bn != 0) return;
#pragma unroll
        for (int mt = 0; mt < 4; ++mt) {
            int row0 = bm + wm * 64 + mt * 16 + (lane >> 2);
#pragma unroll
            for (int nt = 0; nt < 4; ++nt) {
#pragma unroll
                for (int half = 0; half < 2; ++half) {
#pragma unroll
                    for (int e = 0; e < 2; ++e) {
                        int col = nt * 8 + (lane & 3) * 2 + e;
                        int t = row0 + half * 8;
                        float v = acc[mt][nt][half * 2 + e];
                        if (col < 16) {
                            beta_out[col * SEQ + t] = 1.f / (1.f + expf(-v));
                        } else {
                            int h = col - 16;
                            float z = v + dt_bias[h];
                            float sp = (z > 20.f) ? z : log1pf(expf(z));
                            alpha_out[h * SEQ + t] = expf(-expf(log_A[h]) * sp);
                        }
                    }
                }
            }
        }
        return;
    }
#pragma unroll
    for (int mt = 0; mt < 4; ++mt) {
        int row0 = bm + wm * 64 + mt * 16 + (lane >> 2);
#pragma unroll
        for (int nt = 0; nt < 4; ++nt) {
            int col = bn + wn * 32 + nt * 8 + (lane & 3) * 2;
            float2 v0 = make_float2(acc[mt][nt][0], acc[mt][nt][1]);
            float2 v1 = make_float2(acc[mt][nt][2], acc[mt][nt][3]);
            if (epi == 1) {
                v0.x = silu(v0.x); v0.y = silu(v0.y);
                v1.x = silu(v1.x); v1.y = silu(v1.y);
            }
            *(float2*)(Cp + (size_t)row0 * N + col) = v0;
            *(float2*)(Cp + (size_t)(row0 + 8) * N + col) = v1;
        }
    }
}

// ---------------------------------------------------------------------------
// one-shot fp32 -> (bf16 hi, lo) split over all operands
// ---------------------------------------------------------------------------
#define N4_X   (SEQ * DIN / 4)
#define N4_QKV (FUSEDC * DIN / 4)
#define N4_WG  (DOVG * DIN / 4)
#define N4_WO  (DOVG * DIN / 4)
#define N4_WB  (16 * DIN / 4)
#define N4_WA  (16 * DIN / 4)
#define N4_TOT (N4_X + N4_QKV + N4_WG + N4_WO + N4_WB + N4_WA)

__global__ void __launch_bounds__(256) split_all(
    const float* __restrict__ x, const float* __restrict__ wqkv,
    const float* __restrict__ wg, const float* __restrict__ wo,
    const float* __restrict__ wb, const float* __restrict__ wa,
    __nv_bfloat16* xh, __nv_bfloat16* xl,
    __nv_bfloat16* qh, __nv_bfloat16* ql,
    __nv_bfloat16* gh, __nv_bfloat16* gl,
    __nv_bfloat16* oh, __nv_bfloat16* ol,
    __nv_bfloat16* bah, __nv_bfloat16* bal)
{
    int i = blockIdx.x * 256 + threadIdx.x;
    if (i >= N4_TOT) return;
    const float* src;
    __nv_bfloat16 *hi, *lo;
    if (i < N4_X) { src = x; hi = xh; lo = xl; }
    else if ((i -= N4_X) < N4_QKV) { src = wqkv; hi = qh; lo = ql; }
    else if ((i -= N4_QKV) < N4_WG) { src = wg; hi = gh; lo = gl; }
    else if ((i -= N4_WG) < N4_WO) { src = wo; hi = oh; lo = ol; }
    else if ((i -= N4_WO) < N4_WB) { src = wb; hi = bah; lo = bal; }
    else { i -= N4_WB; src = wa; hi = bah + 16 * DIN; lo = bal + 16 * DIN; }

    float4 v = ((const float4*)src)[i];
    __nv_bfloat16 h0 = __float2bfloat16(v.x), h1 = __float2bfloat16(v.y);
    __nv_bfloat16 h2 = __float2bfloat16(v.z), h3 = __float2bfloat16(v.w);
    __nv_bfloat16 l0 = __float2bfloat16(v.x - __bfloat162float(h0));
    __nv_bfloat16 l1 = __float2bfloat16(v.y - __bfloat162float(h1));
    __nv_bfloat16 l2 = __float2bfloat16(v.z - __bfloat162float(h2));
    __nv_bfloat16 l3 = __float2bfloat16(v.w - __bfloat162float(h3));
    ((__nv_bfloat162*)hi)[i * 2 + 0] = __halves2bfloat162(h0, h1);
    ((__nv_bfloat162*)hi)[i * 2 + 1] = __halves2bfloat162(h2, h3);
    ((__nv_bfloat162*)lo)[i * 2 + 0] = __halves2bfloat162(l0, l1);
    ((__nv_bfloat162*)lo)[i * 2 + 1] = __halves2bfloat162(l2, l3);
}

// ---------------------------------------------------------------------------
// causal depthwise conv1d (K=4) + SiLU + fused l2norm for q/k head blocks
// ---------------------------------------------------------------------------
__global__ void __launch_bounds__(128) conv_l2_kernel(
    const float* __restrict__ in, const float* __restrict__ w,
    float* __restrict__ out)
{
    const int t0  = blockIdx.x * 4;
    const int blk = blockIdx.y;
    const int tid = threadIdx.x;
    const int c   = blk * 128 + tid;
    const int lane = tid & 31;
    const int wrp  = tid >> 5;

    float4 wc = *(const float4*)(w + c * 4);
    const float* col = in + c;

    float p1 = (t0 >= 1) ? col[(size_t)(t0 - 1) * FUSEDC] : 0.f;
    float p2 = (t0 >= 2) ? col[(size_t)(t0 - 2) * FUSEDC] : 0.f;
    float p3 = (t0 >= 3) ? col[(size_t)(t0 - 3) * FUSEDC] : 0.f;
    float c0 = col[(size_t)(t0 + 0) * FUSEDC];
    float c1 = col[(size_t)(t0 + 1) * FUSEDC];
    float c2 = col[(size_t)(t0 + 2) * FUSEDC];
    float c3 = col[(size_t)(t0 + 3) * FUSEDC];

    float v[4];
    v[0] = silu(wc.w * c0 + wc.z * p1 + wc.y * p2 + wc.x * p3);
    v[1] = silu(wc.w * c1 + wc.z * c0 + wc.y * p1 + wc.x * p2);
    v[2] = silu(wc.w * c2 + wc.z * c1 + wc.y * c0 + wc.x * p1);
    v[3] = silu(wc.w * c3 + wc.z * c2 + wc.y * c1 + wc.x * c0);

    if (blk < 16) {
        __shared__ float sred[4][128];
        __shared__ float sscale[4];
#pragma unroll
        for (int i = 0; i < 4; ++i) sred[i][tid] = v[i] * v[i];
        __syncthreads();
        float s = sred[wrp][lane] + sred[wrp][lane + 32] +
                  sred[wrp][lane + 64] + sred[wrp][lane + 96];
#pragma unroll
        for (int m = 16; m; m >>= 1) s += __shfl_xor_sync(0xffffffffu, s, m);
        if (lane == 0) {
            float sc = rsqrtf(s + 1e-6f);
            if (blk < 8) sc *= 0.08838834764831845f;
            sscale[wrp] = sc;
        }
        __syncthreads();
#pragma unroll
        for (int i = 0; i < 4; ++i) v[i] *= sscale[i];
    }
#pragma unroll
    for (int i = 0; i < 4; ++i)
        out[(size_t)(t0 + i) * FUSEDC + c] = v[i];
}

// ---------------------------------------------------------------------------
// Gated delta-rule scan.
// grid 256 = 16 heads x 16 col-blocks (8 cols); 128 threads (16 subs x 8 cols)
// Smem q/k rows stored with 16B-chunk XOR swizzle c^(c>>3): the per-step
// kr/qr LDS.128 across the 16 subs are bank-conflict-free.
// Per buf (floats): q 4096 | k 4096 | v 256 | b 32 | a 32 = 8512
// ---------------------------------------------------------------------------
#define TSCHUNK 32
#define SC_K   4096
#define SC_V   8192
#define SC_B   8448
#define SC_A   8480
#define SCAN_BUF_F 8512
#define SCAN_SMEM (2 * SCAN_BUF_F * 4)

__global__ void __launch_bounds__(128) scan_kernel(
    const float* __restrict__ qkv, const float* __restrict__ beta,
    const float* __restrict__ alpha, float* __restrict__ ctx)
{
    extern __shared__ float ss[];
    const int h  = blockIdx.x >> 4;
    const int cb = blockIdx.x & 15;
    const int hq = h >> 1;
    const int tid  = threadIdx.x;
    const int j    = tid >> 4;        // 0..7 column
    const int sub  = tid & 15;        // 0..15 row group (8 rows)

    const uint32_t ssb = smem_u32(ss);

    const float* qbase = qkv + hq * 128;
    const float* kbase = qkv + 1024 + hq * 128;
    const float* vbase = qkv + 2048 + h * 128 + cb * 8;
    const float* bbase = beta + h * SEQ;
    const float* abase = alpha + h * SEQ;
    float* obase = ctx + h * 128 + cb * 8 + j;

    // swizzled per-thread load offsets (float index within a 128-float row)
    const int c0 = sub * 2;
    const int c0s = c0 ^ (c0 >> 3);
    const int c1 = c0 + 1;
    const int c1s = c1 ^ (c1 >> 3);

#define SCAN_ISSUE(buf, t0)                                                    \
    do {                                                                       \
        uint32_t sbb = ssb + (uint32_t)(buf) * (SCAN_BUF_F * 4);               \
        _Pragma("unroll")                                                      \
        for (int u = 0; u < 8; ++u) {                                          \
            int lin = tid + u * 128;                                           \
            int tt = lin >> 5, d4 = lin & 31;                                  \
            int sw = d4 ^ (d4 >> 3);                                           \
            size_t goff = (size_t)((t0) + tt) * FUSEDC + d4 * 4;               \
            uint32_t so = (uint32_t)(tt * 32 + sw) * 16;                       \
            cp_async16(sbb + so, qbase + goff);                                \
            cp_async16(sbb + SC_K * 4 + so, kbase + goff);                     \
        }                                                                      \
        if (tid < 64) {                                                        \
            int tt = tid >> 1, j4 = tid & 1;                                   \
            cp_async16(sbb + SC_V * 4 + (uint32_t)tid * 16,                    \
                       vbase + (size_t)((t0) + tt) * FUSEDC + j4 * 4);         \
        } else if (tid < 96) {                                                 \
            cp_async4(sbb + SC_B * 4 + (uint32_t)(tid - 64) * 4,               \
                      bbase + (t0) + tid - 64);                                \
        } else {                                                               \
            cp_async4(sbb + SC_A * 4 + (uint32_t)(tid - 96) * 4,               \
                      abase + (t0) + tid - 96);                                \
        }                                                                      \
        cp_commit();                                                           \
    } while (0)

    float S[8];
#pragma unroll
    for (int i = 0; i < 8; ++i) S[i] = 0.f;

    SCAN_ISSUE(0, 0);

    for (int ci = 0; ci < SEQ / TSCHUNK; ++ci) {
        asm volatile("cp.async.wait_group 0;");
        __syncthreads();
        if (ci + 1 < SEQ / TSCHUNK) SCAN_ISSUE((ci + 1) & 1, (ci + 1) * TSCHUNK);

        const float* sqf = ss + (ci & 1) * SCAN_BUF_F;
        const float* skf = sqf + SC_K;
        const float* svf = sqf + SC_V;
        const float* sbf = sqf + SC_B;
        const float* saf = sqf + SC_A;
        const int t0 = ci * TSCHUNK;

#pragma unroll 4
        for (int tt = 0; tt < TSCHUNK; ++tt) {
            // off-chain per-step scalars
            float a = saf[tt], b = sbf[tt];
            float bv = b * svf[tt * 8 + j];
            float ab = a * b;
            float kr[8], qr[8];
            *(float4*)(kr)     = *(const float4*)&skf[tt * 128 + c0s * 4];
            *(float4*)(kr + 4) = *(const float4*)&skf[tt * 128 + c1s * 4];
            *(float4*)(qr)     = *(const float4*)&sqf[tt * 128 + c0s * 4];
            *(float4*)(qr + 4) = *(const float4*)&sqf[tt * 128 + c1s * 4];

            float kv0 = 0.f, kv1 = 0.f;
#pragma unroll
            for (int i = 0; i < 8; i += 2) {
                kv0 = fmaf(kr[i],     S[i],     kv0);
                kv1 = fmaf(kr[i + 1], S[i + 1], kv1);
            }
            float kv = kv0 + kv1;
            kv += __shfl_xor_sync(0xffffffffu, kv, 1);
            kv += __shfl_xor_sync(0xffffffffu, kv, 2);
            kv += __shfl_xor_sync(0xffffffffu, kv, 4);
            kv += __shfl_xor_sync(0xffffffffu, kv, 8);
            float uval = fmaf(-ab, kv, bv);     // one FMA on the chain
            float o0 = 0.f, o1 = 0.f;
#pragma unroll
            for (int i = 0; i < 8; ++i)
                S[i] = fmaf(a, S[i], kr[i] * uval);
#pragma unroll
            for (int i = 0; i < 8; i += 2) {
                o0 = fmaf(qr[i],     S[i],     o0);
                o1 = fmaf(qr[i + 1], S[i + 1], o1);
            }
            float o = o0 + o1;
            o += __shfl_xor_sync(0xffffffffu, o, 1);
            o += __shfl_xor_sync(0xffffffffu, o, 2);
            o += __shfl_xor_sync(0xffffffffu, o, 4);
            o += __shfl_xor_sync(0xffffffffu, o, 8);
            if (sub == 0) obase[(size_t)(t0 + tt) * DOVG] = o;
        }
        __syncthreads();
    }
#undef SCAN_ISSUE
}

// ---------------------------------------------------------------------------
// rms_norm(ctx) * rms_w * gate -> split bf16 (hi/lo)
// ---------------------------------------------------------------------------
__global__ void __launch_bounds__(128) rms_gate_kernel(
    const float* __restrict__ ctx, const float* __restrict__ gate,
    const float* __restrict__ rms_w,
    __nv_bfloat16* __restrict__ ghi, __nv_bfloat16* __restrict__ glo)
{
    const int t = blockIdx.x;
    const int h = blockIdx.y;
    const int tid = threadIdx.x;
    size_t idx = (size_t)t * DOVG + h * 128 + tid;
    float v = ctx[idx];
    float ss = v * v;
#pragma unroll
    for (int m = 16; m; m >>= 1) ss += __shfl_xor_sync(0xffffffffu, ss, m);
    __shared__ float sw[4];
    if ((tid & 31) == 0) sw[tid >> 5] = ss;
    __syncthreads();
    float tot = sw[0] + sw[1] + sw[2] + sw[3];
    float sc = rsqrtf(tot * (1.f / 128.f) + 1e-6f);
    float r = v * sc * rms_w[tid] * gate[idx];
    __nv_bfloat16 hh = __float2bfloat16(r);
    ghi[idx] = hh;
    glo[idx] = __float2bfloat16(r - __bfloat162float(hh));
}

// ---------------------------------------------------------------------------
extern "C" void kernel_launch(void* const* d_in, const int* in_sizes, int n_in,
                              void* d_out, int out_size)
{
    const float* x       = (const float*)d_in[0];
    const float* w_qkv   = (const float*)d_in[1];
    const float* w_gate  = (const float*)d_in[2];
    const float* w_beta  = (const float*)d_in[3];
    const float* w_alpha = (const float*)d_in[4];
    const float* log_A   = (const float*)d_in[5];
    const float* dt_bias = (const float*)d_in[6];
    const float* conv_w  = (const float*)d_in[7];
    const float* rms_w   = (const float*)d_in[8];
    const float* w_out   = (const float*)d_in[9];
    float* out = (float*)d_out;

    float *qkv_pre, *qkv, *gate, *ctx, *beta, *alpha;
    __nv_bfloat16 *x_hi, *x_lo, *wqkv_hi, *wqkv_lo, *wg_hi, *wg_lo,
                  *wo_hi, *wo_lo, *gctx_hi, *gctx_lo, *wba_hi, *wba_lo;
    cudaGetSymbolAddress((void**)&qkv_pre, g_qkv_pre);
    cudaGetSymbolAddress((void**)&qkv,     g_qkv);
    cudaGetSymbolAddress((void**)&gate,    g_gate);
    cudaGetSymbolAddress((void**)&ctx,     g_ctx);
    cudaGetSymbolAddress((void**)&beta,    g_beta);
    cudaGetSymbolAddress((void**)&alpha,   g_alpha);
    cudaGetSymbolAddress((void**)&x_hi,    g_x_hi);
    cudaGetSymbolAddress((void**)&x_lo,    g_x_lo);
    cudaGetSymbolAddress((void**)&wqkv_hi, g_wqkv_hi);
    cudaGetSymbolAddress((void**)&wqkv_lo, g_wqkv_lo);
    cudaGetSymbolAddress((void**)&wg_hi,   g_wg_hi);
    cudaGetSymbolAddress((void**)&wg_lo,   g_wg_lo);
    cudaGetSymbolAddress((void**)&wo_hi,   g_wo_hi);
    cudaGetSymbolAddress((void**)&wo_lo,   g_wo_lo);
    cudaGetSymbolAddress((void**)&gctx_hi, g_gctx_hi);
    cudaGetSymbolAddress((void**)&gctx_lo, g_gctx_lo);
    cudaGetSymbolAddress((void**)&wba_hi,  g_wba_hi);
    cudaGetSymbolAddress((void**)&wba_lo,  g_wba_lo);

    cudaFuncSetAttribute(gemm3c, cudaFuncAttributeMaxDynamicSharedMemorySize, GSMEM);
    cudaFuncSetAttribute(scan_kernel, cudaFuncAttributeMaxDynamicSharedMemorySize, SCAN_SMEM);

    // 0) one-shot precision splits
    split_all<<<(N4_TOT + 255) / 256, 256>>>(
        x, w_qkv, w_gate, w_out, w_beta, w_alpha,
        x_hi, x_lo, wqkv_hi, wqkv_lo, wg_hi, wg_lo, wo_hi, wo_lo, wba_hi, wba_lo);

    // 1) fused qkv + gate + beta/alpha projections
    gemm3c<<<dim3((FUSEDC + DOVG + 128) / 128, SEQ / 128), 256, GSMEM>>>(
        x_hi, x_lo,
        wqkv_hi, wqkv_lo, qkv_pre, FUSEDC, 0,
        wg_hi, wg_lo, gate, DOVG, 1,
        wba_hi, wba_lo, 128,
        log_A, dt_bias, beta, alpha);

    // 2) causal depthwise conv + silu + fused l2norm on q/k
    conv_l2_kernel<<<dim3(SEQ / 4, 32), 128>>>(qkv_pre, conv_w, qkv);

    // 3) gated delta-rule scan
    scan_kernel<<<256, 128, SCAN_SMEM>>>(qkv, beta, alpha, ctx);

    // 4) rms norm * gate -> split bf16
    rms_gate_kernel<<<dim3(SEQ, HV), 128>>>(ctx, gate, rms_w, gctx_hi, gctx_lo);

    // 5) output projection
    gemm3c<<<dim3(DOVG / 128, SEQ / 128), 256, GSMEM>>>(
        gctx_hi, gctx_lo,
        wo_hi, wo_lo, out, DOVG, 0,
        (const __nv_bfloat16*)0, (const __nv_bfloat16*)0, (float*)0, 0, 0,
        (const __nv_bfloat16*)0, (const __nv_bfloat16*)0, 0,
        log_A, dt_bias, beta, alpha);
}